// round 1
// baseline (speedup 1.0000x reference)
#include <cuda_runtime.h>
#include <math.h>

#define BB   2
#define TT   2048
#define DD   2048
#define NH   16
#define NKV  4
#define HDQ  128
#define BT   4096   // BB*TT

// ---------------- scratch (static device globals: no allocs allowed) --------
__device__ float g_Q[(size_t)BT * (NH * HDQ)];   // 33.5 MB
__device__ float g_K[(size_t)BT * (NKV * HDQ)];  // 8.4 MB
__device__ float g_V[(size_t)BT * (NKV * HDQ)];  // 8.4 MB
__device__ float g_A[(size_t)BT * (NH * HDQ)];   // 33.5 MB

// ---------------- SGEMM: C[M,N] = A[M,K] @ B[K,N], row-major ----------------
// 128x128 block tile, BK=8, 256 threads, 8x8 micro-tile per thread.
__global__ __launch_bounds__(256) void sgemm_kernel(
    const float* __restrict__ A, const float* __restrict__ B,
    float* __restrict__ C, int M, int N, int K)
{
    __shared__ float As[8][128];   // transposed A tile
    __shared__ float Bs[8][128];

    const int tid = threadIdx.x;
    const int tx = tid & 15;
    const int ty = tid >> 4;
    const int mBase = blockIdx.y << 7;
    const int nBase = blockIdx.x << 7;

    const int lm  = tid >> 1;          // 0..127
    const int lk4 = (tid & 1) << 2;    // 0 or 4
    const int lbk = tid >> 5;          // 0..7
    const int lbc = (tid & 31) << 2;   // 0..124

    float acc[8][8];
    #pragma unroll
    for (int i = 0; i < 8; ++i)
        #pragma unroll
        for (int j = 0; j < 8; ++j) acc[i][j] = 0.f;

    const float* Ap = A + (size_t)(mBase + lm) * K + lk4;
    const float* Bp = B + (size_t)lbk * N + nBase + lbc;

    for (int kb = 0; kb < K; kb += 8) {
        float4 av = *(const float4*)(Ap + kb);
        As[lk4 + 0][lm] = av.x;
        As[lk4 + 1][lm] = av.y;
        As[lk4 + 2][lm] = av.z;
        As[lk4 + 3][lm] = av.w;
        float4 bv = *(const float4*)(Bp + (size_t)kb * N);
        *(float4*)&Bs[lbk][lbc] = bv;
        __syncthreads();
        #pragma unroll
        for (int k = 0; k < 8; ++k) {
            float a[8], b[8];
            #pragma unroll
            for (int i = 0; i < 8; ++i) a[i] = As[k][i * 16 + ty];
            #pragma unroll
            for (int j = 0; j < 8; ++j) b[j] = Bs[k][j * 16 + tx];
            #pragma unroll
            for (int i = 0; i < 8; ++i)
                #pragma unroll
                for (int j = 0; j < 8; ++j)
                    acc[i][j] = fmaf(a[i], b[j], acc[i][j]);
        }
        __syncthreads();
    }

    #pragma unroll
    for (int i = 0; i < 8; ++i) {
        float* Cp = C + (size_t)(mBase + i * 16 + ty) * N + nBase;
        #pragma unroll
        for (int j = 0; j < 8; ++j)
            Cp[j * 16 + tx] = acc[i][j];
    }
}

// ---------------- RoPE (in place). cols = n_heads*128. -----------------------
// out[d]     = u[d]*cos - u[d+64]*sin     (d in [0,64))
// out[d+64]  = u[d+64]*cos + u[d]*sin,  angle = t * theta^(-d/64)
__global__ void rope_kernel(float* __restrict__ buf, int cols)
{
    int idx = blockIdx.x * blockDim.x + threadIdx.x;
    int ppr = cols >> 1;           // pairs per row
    int total = BT * ppr;
    if (idx >= total) return;
    int row = idx / ppr;
    int p   = idx - row * ppr;
    int h   = p >> 6;
    int d   = p & 63;
    int t   = row & (TT - 1);      // row % T
    size_t base = (size_t)row * cols + h * 128 + d;
    float u1 = buf[base];
    float u2 = buf[base + 64];
    // angle in double for a clean error budget (cheap: tiny kernel)
    double inv = exp2(-(double)d * (19.931568569324174 / 64.0)); // 1e6^(-d/64)
    double ang = (double)t * inv;
    float c = (float)cos(ang);
    float s = (float)sin(ang);
    buf[base]      = u1 * c - u2 * s;
    buf[base + 64] = u2 * c + u1 * s;
}

// ---------------- Flash attention (causal, GQA, fp32) ------------------------
// Grid: (T/64 q-tiles, NH, BB). Block: 256 threads (16x16 thread grid).
// Per thread: 4 query rows (ty*4+i), S cols j*16+tx (j<4), O cols j*16+tx (j<8).
#define AT_SMEM_FLOATS (128 * 65 * 2 + 64 * 132 + 64 * 65)
#define AT_SMEM_BYTES  (AT_SMEM_FLOATS * sizeof(float))

__global__ __launch_bounds__(256) void attn_kernel(
    const float* __restrict__ Q, const float* __restrict__ K,
    const float* __restrict__ V, float* __restrict__ O)
{
    extern __shared__ float sm[];
    float* QsT = sm;                  // [128][65]  (d-major, conflict-free)
    float* KsT = QsT + 128 * 65;      // [128][65]
    float* Vs  = KsT + 128 * 65;      // [64][132]  (key-major)
    float* Ps  = Vs  + 64 * 132;      // [64][65]

    const int tid = threadIdx.x;
    const int tx  = tid & 15;
    const int ty  = tid >> 4;
    const int qt  = gridDim.x - 1 - blockIdx.x;  // heavy tiles first
    const int h   = blockIdx.y;
    const int b   = blockIdx.z;
    const int hk  = h >> 2;                       // GQA: 4 q-heads per kv-head
    const int qBase = qt * 64;
    const float scale = 0.08838834764831845f;     // 1/sqrt(128)

    // Load Q tile transposed: QsT[d][j]
    {
        const float* Qp = Q + ((size_t)b * TT + qBase) * (NH * HDQ) + h * HDQ;
        for (int idx = tid; idx < 64 * 128; idx += 256) {
            int j = idx >> 7;
            int d = idx & 127;
            QsT[d * 65 + j] = Qp[(size_t)j * (NH * HDQ) + d];
        }
    }

    float m[4], l[4], acc[4][8];
    #pragma unroll
    for (int i = 0; i < 4; ++i) { m[i] = -INFINITY; l[i] = 0.f; }
    #pragma unroll
    for (int i = 0; i < 4; ++i)
        #pragma unroll
        for (int j = 0; j < 8; ++j) acc[i][j] = 0.f;

    for (int kt = 0; kt <= qt; ++kt) {
        const float* Kp = K + ((size_t)b * TT + kt * 64) * (NKV * HDQ) + hk * HDQ;
        const float* Vp = V + ((size_t)b * TT + kt * 64) * (NKV * HDQ) + hk * HDQ;
        for (int idx = tid; idx < 64 * 128; idx += 256) {
            int j = idx >> 7;
            int d = idx & 127;
            KsT[d * 65 + j] = Kp[(size_t)j * (NKV * HDQ) + d];
        }
        for (int idx = tid; idx < 64 * 32; idx += 256) {
            int j  = idx >> 5;
            int d4 = (idx & 31) << 2;
            float4 vv = *(const float4*)(Vp + (size_t)j * (NKV * HDQ) + d4);
            *(float4*)&Vs[j * 132 + d4] = vv;
        }
        __syncthreads();

        // S = Q @ K^T  (4x4 per thread, S col = j*16+tx)
        float s[4][4];
        #pragma unroll
        for (int i = 0; i < 4; ++i)
            #pragma unroll
            for (int j = 0; j < 4; ++j) s[i][j] = 0.f;
        #pragma unroll 8
        for (int k = 0; k < 128; ++k) {
            float q[4], kv[4];
            #pragma unroll
            for (int i = 0; i < 4; ++i) q[i]  = QsT[k * 65 + ty * 4 + i];
            #pragma unroll
            for (int j = 0; j < 4; ++j) kv[j] = KsT[k * 65 + j * 16 + tx];
            #pragma unroll
            for (int i = 0; i < 4; ++i)
                #pragma unroll
                for (int j = 0; j < 4; ++j)
                    s[i][j] = fmaf(q[i], kv[j], s[i][j]);
        }
        #pragma unroll
        for (int i = 0; i < 4; ++i)
            #pragma unroll
            for (int j = 0; j < 4; ++j) s[i][j] *= scale;

        if (kt == qt) {  // causal mask only touches the diagonal tile
            #pragma unroll
            for (int i = 0; i < 4; ++i) {
                int qi = qBase + ty * 4 + i;
                #pragma unroll
                for (int j = 0; j < 4; ++j)
                    if (kt * 64 + j * 16 + tx > qi) s[i][j] = -1e30f;
            }
        }

        // Online softmax (row spread over 16 lanes sharing ty)
        #pragma unroll
        for (int i = 0; i < 4; ++i) {
            float rmax = fmaxf(fmaxf(s[i][0], s[i][1]), fmaxf(s[i][2], s[i][3]));
            #pragma unroll
            for (int off = 8; off; off >>= 1)
                rmax = fmaxf(rmax, __shfl_xor_sync(0xffffffffu, rmax, off));
            float mnew = fmaxf(m[i], rmax);
            float f = __expf(m[i] - mnew);
            m[i] = mnew;
            float rsum = 0.f;
            #pragma unroll
            for (int j = 0; j < 4; ++j) {
                s[i][j] = __expf(s[i][j] - mnew);
                rsum += s[i][j];
            }
            #pragma unroll
            for (int off = 8; off; off >>= 1)
                rsum += __shfl_xor_sync(0xffffffffu, rsum, off);
            l[i] = l[i] * f + rsum;
            #pragma unroll
            for (int j = 0; j < 8; ++j) acc[i][j] *= f;
        }

        // Stage P, then O += P @ V
        #pragma unroll
        for (int i = 0; i < 4; ++i)
            #pragma unroll
            for (int j = 0; j < 4; ++j)
                Ps[(ty * 4 + i) * 65 + j * 16 + tx] = s[i][j];
        __syncthreads();

        #pragma unroll 4
        for (int kk = 0; kk < 64; ++kk) {
            float p[4], v[8];
            #pragma unroll
            for (int i = 0; i < 4; ++i) p[i] = Ps[(ty * 4 + i) * 65 + kk];
            #pragma unroll
            for (int j = 0; j < 8; ++j) v[j] = Vs[kk * 132 + j * 16 + tx];
            #pragma unroll
            for (int i = 0; i < 4; ++i)
                #pragma unroll
                for (int j = 0; j < 8; ++j)
                    acc[i][j] = fmaf(p[i], v[j], acc[i][j]);
        }
        __syncthreads();
    }

    #pragma unroll
    for (int i = 0; i < 4; ++i) {
        float invl = 1.f / l[i];
        float* Op = O + ((size_t)b * TT + qBase + ty * 4 + i) * (NH * HDQ) + h * HDQ;
        #pragma unroll
        for (int j = 0; j < 8; ++j)
            Op[j * 16 + tx] = acc[i][j] * invl;
    }
}

// ---------------- launcher ---------------------------------------------------
extern "C" void kernel_launch(void* const* d_in, const int* in_sizes, int n_in,
                              void* d_out, int out_size)
{
    const float* x  = (const float*)d_in[0];
    const float* wq = (const float*)d_in[1];
    const float* wk = (const float*)d_in[2];
    const float* wv = (const float*)d_in[3];
    const float* wo = (const float*)d_in[4];
    float* out = (float*)d_out;

    float *Qb, *Kb, *Vb, *Ab;
    cudaGetSymbolAddress((void**)&Qb, g_Q);
    cudaGetSymbolAddress((void**)&Kb, g_K);
    cudaGetSymbolAddress((void**)&Vb, g_V);
    cudaGetSymbolAddress((void**)&Ab, g_A);

    cudaFuncSetAttribute(attn_kernel,
                         cudaFuncAttributeMaxDynamicSharedMemorySize,
                         (int)AT_SMEM_BYTES);

    dim3 blk(256);
    // QKV projections
    sgemm_kernel<<<dim3(2048 / 128, 4096 / 128), blk>>>(x, wq, Qb, BT, 2048, 2048);
    sgemm_kernel<<<dim3(512 / 128, 4096 / 128), blk>>>(x, wk, Kb, BT, 512, 2048);
    sgemm_kernel<<<dim3(512 / 128, 4096 / 128), blk>>>(x, wv, Vb, BT, 512, 2048);
    // RoPE on Q and K
    rope_kernel<<<(BT * 1024 + 255) / 256, 256>>>(Qb, 2048);
    rope_kernel<<<(BT * 256 + 255) / 256, 256>>>(Kb, 512);
    // Flash attention
    attn_kernel<<<dim3(TT / 64, NH, BB), blk, AT_SMEM_BYTES>>>(Qb, Kb, Vb, Ab);
    // Output projection
    sgemm_kernel<<<dim3(2048 / 128, 4096 / 128), blk>>>(Ab, wo, out, BT, 2048, 2048);
}

// round 3
// speedup vs baseline: 1.7804x; 1.7804x over previous
#include <cuda_runtime.h>
#include <cuda_bf16.h>
#include <math.h>
#include <stdint.h>

#define BB   2
#define TT   2048
#define DD   2048
#define NH   16
#define NKV  4
#define HDQ  128
#define BT   4096   // BB*TT
#define KDIM 2048

// ---------------- scratch (static device globals: no allocs allowed) --------
__device__ float g_Q[(size_t)BT * (NH * HDQ)];
__device__ float g_K[(size_t)BT * (NKV * HDQ)];
__device__ float g_V[(size_t)BT * (NKV * HDQ)];
__device__ float g_A[(size_t)BT * (NH * HDQ)];

__device__ __nv_bfloat16 g_xbf[(size_t)BT * 2 * KDIM];       // x split  [M][2K]
__device__ __nv_bfloat16 g_abf[(size_t)BT * 2 * KDIM];       // attn-out split
__device__ __nv_bfloat16 g_wqt[(size_t)2048 * 2 * KDIM];     // [N][2K]
__device__ __nv_bfloat16 g_wkt[(size_t)512  * 2 * KDIM];
__device__ __nv_bfloat16 g_wvt[(size_t)512  * 2 * KDIM];
__device__ __nv_bfloat16 g_wot[(size_t)2048 * 2 * KDIM];
__device__ float g_rcos[TT * 64];
__device__ float g_rsin[TT * 64];

// ---------------- helpers ----------------------------------------------------
__device__ __forceinline__ uint32_t smem_u32(const void* p) {
    uint32_t a;
    asm("{ .reg .u64 t; cvta.to.shared.u64 t, %1; cvt.u32.u64 %0, t; }"
        : "=r"(a) : "l"(p));
    return a;
}
__device__ __forceinline__ void ldm_x4(uint32_t& r0, uint32_t& r1,
                                       uint32_t& r2, uint32_t& r3, uint32_t addr) {
    asm volatile("ldmatrix.sync.aligned.m8n8.x4.shared.b16 {%0,%1,%2,%3}, [%4];"
                 : "=r"(r0), "=r"(r1), "=r"(r2), "=r"(r3) : "r"(addr));
}
__device__ __forceinline__ void mma16816(float* d, const uint32_t* a, const uint32_t* b) {
    asm volatile("mma.sync.aligned.m16n8k16.row.col.f32.bf16.bf16.f32 "
                 "{%0,%1,%2,%3}, {%4,%5,%6,%7}, {%8,%9}, {%0,%1,%2,%3};"
                 : "+f"(d[0]), "+f"(d[1]), "+f"(d[2]), "+f"(d[3])
                 : "r"(a[0]), "r"(a[1]), "r"(a[2]), "r"(a[3]),
                   "r"(b[0]), "r"(b[1]));
}

// ---------------- conversion kernels ----------------------------------------
// split: A[M][2048] fp32 -> O[M][4096] bf16 (hi cols 0..2047, lo cols 2048..4095)
__global__ void split_kernel(const float* __restrict__ A, __nv_bfloat16* __restrict__ O)
{
    int idx = blockIdx.x * blockDim.x + threadIdx.x;
    if (idx >= BT * KDIM) return;
    int m = idx >> 11, k = idx & 2047;
    float a = A[idx];
    __nv_bfloat16 h = __float2bfloat16(a);
    __nv_bfloat16 l = __float2bfloat16(a - __bfloat162float(h));
    size_t base = (size_t)m * (2 * KDIM);
    O[base + k] = h;
    O[base + KDIM + k] = l;
}
// transpose+split: W[K=2048][N] fp32 -> Wt[N][2K] bf16 (hi|lo along K)
__global__ void tsplit_kernel(const float* __restrict__ W, __nv_bfloat16* __restrict__ Wt, int N)
{
    __shared__ float tile[32][33];
    int tx = threadIdx.x & 31, ty = threadIdx.x >> 5;
    int nb = blockIdx.x * 32, kb = blockIdx.y * 32;
    #pragma unroll
    for (int r = 0; r < 4; ++r)
        tile[ty + r * 8][tx] = W[(size_t)(kb + ty + r * 8) * N + nb + tx];
    __syncthreads();
    #pragma unroll
    for (int r = 0; r < 4; ++r) {
        int n = nb + ty + r * 8;
        float a = tile[tx][ty + r * 8];
        __nv_bfloat16 h = __float2bfloat16(a);
        __nv_bfloat16 l = __float2bfloat16(a - __bfloat162float(h));
        size_t base = (size_t)n * (2 * KDIM) + kb + tx;
        Wt[base] = h;
        Wt[base + KDIM] = l;
    }
}

// ---------------- bf16x3 GEMM via mma.sync -----------------------------------
// C[M,N] = A[M,2K](hi|lo) @ Bt[N,2K](hi|lo)^T over passes hi*hi + hi*lo + lo*hi.
// 128x128x32 tile, 256 threads, 8 warps (4m x 2n), warp tile 32x64.
__global__ __launch_bounds__(256, 2) void gemm3_kernel(
    const __nv_bfloat16* __restrict__ A, const __nv_bfloat16* __restrict__ Bt,
    float* __restrict__ C, int N, int K)
{
    __shared__ __nv_bfloat16 As[2][128][40];   // stride 40: 80B rows, ldmatrix conflict-free
    __shared__ __nv_bfloat16 Bs[2][128][40];

    const int tid = threadIdx.x;
    const int lane = tid & 31, wid = tid >> 5;
    const int wm = wid & 3, wn = wid >> 2;
    const int mBase = blockIdx.y << 7, nBase = blockIdx.x << 7;
    const int twoK = 2 * K;
    const int KC = K >> 5;           // 32-wide chunks per pass
    const int NC = 3 * KC;

    const int lrow = tid >> 1;           // gmem load: row 0..127
    const int lseg = (tid & 1) << 4;     // 0 or 16 elements

    // ldmatrix lane-address components
    const int ldRow = lane & 15;
    const int ldCol = (lane >> 4) << 3;

    float acc[2][8][4];
    #pragma unroll
    for (int i = 0; i < 2; ++i)
        #pragma unroll
        for (int j = 0; j < 8; ++j)
            #pragma unroll
            for (int r = 0; r < 4; ++r) acc[i][j][r] = 0.f;

    // prologue: chunk 0 (p=0: hi/hi) into buffer 0
    {
        const __nv_bfloat16* ga = A  + (size_t)(mBase + lrow) * twoK + lseg;
        const __nv_bfloat16* gb = Bt + (size_t)(nBase + lrow) * twoK + lseg;
        *(uint4*)&As[0][lrow][lseg]     = *(const uint4*)ga;
        *(uint4*)&As[0][lrow][lseg + 8] = *(const uint4*)(ga + 8);
        *(uint4*)&Bs[0][lrow][lseg]     = *(const uint4*)gb;
        *(uint4*)&Bs[0][lrow][lseg + 8] = *(const uint4*)(gb + 8);
    }
    __syncthreads();

    for (int c = 0; c < NC; ++c) {
        const int b = c & 1;
        uint4 ra0, ra1, rb0, rb1;
        const bool pf = (c + 1 < NC);
        if (pf) {
            int cn = c + 1;
            int p = cn / KC, kc = cn - p * KC;
            int aoff = kc * 32 + (p == 2 ? K : 0);
            int boff = kc * 32 + (p == 1 ? K : 0);
            const __nv_bfloat16* ga = A  + (size_t)(mBase + lrow) * twoK + aoff + lseg;
            const __nv_bfloat16* gb = Bt + (size_t)(nBase + lrow) * twoK + boff + lseg;
            ra0 = *(const uint4*)ga; ra1 = *(const uint4*)(ga + 8);
            rb0 = *(const uint4*)gb; rb1 = *(const uint4*)(gb + 8);
        }

        const uint32_t sA = smem_u32(&As[b][0][0]);
        const uint32_t sB = smem_u32(&Bs[b][0][0]);
        #pragma unroll
        for (int ks = 0; ks < 2; ++ks) {
            uint32_t af[2][4], bfr[8][2];
            #pragma unroll
            for (int mf = 0; mf < 2; ++mf) {
                uint32_t addr = sA + ((wm * 32 + mf * 16 + ldRow) * 40
                                      + ks * 16 + ldCol) * 2;
                ldm_x4(af[mf][0], af[mf][1], af[mf][2], af[mf][3], addr);
            }
            #pragma unroll
            for (int ng = 0; ng < 4; ++ng) {
                uint32_t r0, r1, r2, r3;
                uint32_t addr = sB + ((wn * 64 + ng * 16 + ldRow) * 40
                                      + ks * 16 + ldCol) * 2;
                ldm_x4(r0, r1, r2, r3, addr);
                bfr[ng * 2 + 0][0] = r0; bfr[ng * 2 + 1][0] = r1;
                bfr[ng * 2 + 0][1] = r2; bfr[ng * 2 + 1][1] = r3;
            }
            #pragma unroll
            for (int mf = 0; mf < 2; ++mf)
                #pragma unroll
                for (int nf = 0; nf < 8; ++nf)
                    mma16816(acc[mf][nf], af[mf], bfr[nf]);
        }

        if (pf) {
            const int nb = b ^ 1;
            *(uint4*)&As[nb][lrow][lseg]     = ra0;
            *(uint4*)&As[nb][lrow][lseg + 8] = ra1;
            *(uint4*)&Bs[nb][lrow][lseg]     = rb0;
            *(uint4*)&Bs[nb][lrow][lseg + 8] = rb1;
        }
        __syncthreads();
    }

    // epilogue
    const int gid = lane >> 2, tig = lane & 3;
    #pragma unroll
    for (int mf = 0; mf < 2; ++mf) {
        #pragma unroll
        for (int nf = 0; nf < 8; ++nf) {
            int row = mBase + wm * 32 + mf * 16 + gid;
            int col = nBase + wn * 64 + nf * 8 + tig * 2;
            float2 v0 = make_float2(acc[mf][nf][0], acc[mf][nf][1]);
            float2 v1 = make_float2(acc[mf][nf][2], acc[mf][nf][3]);
            *(float2*)&C[(size_t)row * N + col] = v0;
            *(float2*)&C[(size_t)(row + 8) * N + col] = v1;
        }
    }
}

// ---------------- RoPE table + apply -----------------------------------------
__global__ void rope_table_kernel()
{
    int idx = blockIdx.x * blockDim.x + threadIdx.x;
    if (idx >= TT * 64) return;
    int t = idx >> 6, d = idx & 63;
    double inv = exp2(-(double)d * (19.931568569324174 / 64.0)); // 1e6^(-d/64)
    double ang = (double)t * inv;
    g_rcos[idx] = (float)cos(ang);
    g_rsin[idx] = (float)sin(ang);
}
__global__ void rope_kernel(float* __restrict__ buf, int cols)
{
    int idx = blockIdx.x * blockDim.x + threadIdx.x;
    int ppr = cols >> 1;
    int total = BT * ppr;
    if (idx >= total) return;
    int row = idx / ppr;
    int p = idx - row * ppr;
    int h = p >> 6, d = p & 63;
    int t = row & (TT - 1);
    size_t base = (size_t)row * cols + h * 128 + d;
    float u1 = buf[base];
    float u2 = buf[base + 64];
    float c = g_rcos[t * 64 + d];
    float s = g_rsin[t * 64 + d];
    buf[base]      = u1 * c - u2 * s;
    buf[base + 64] = u2 * c + u1 * s;
}

// ---------------- Flash attention (causal, GQA, fp32) ------------------------
#define AT_SMEM_FLOATS (128 * 65 * 2 + 64 * 132 + 64 * 65)
#define AT_SMEM_BYTES  (AT_SMEM_FLOATS * sizeof(float))

__global__ __launch_bounds__(256) void attn_kernel(
    const float* __restrict__ Q, const float* __restrict__ K,
    const float* __restrict__ V, float* __restrict__ O)
{
    extern __shared__ float smf[];
    float* QsT = smf;
    float* KsT = QsT + 128 * 65;
    float* Vs  = KsT + 128 * 65;
    float* Ps  = Vs  + 64 * 132;

    const int tid = threadIdx.x;
    const int tx  = tid & 15;
    const int ty  = tid >> 4;
    const int qt  = gridDim.x - 1 - blockIdx.x;
    const int h   = blockIdx.y;
    const int b   = blockIdx.z;
    const int hk  = h >> 2;
    const int qBase = qt * 64;
    const float scale = 0.08838834764831845f;

    {
        const float* Qp = Q + ((size_t)b * TT + qBase) * (NH * HDQ) + h * HDQ;
        for (int idx = tid; idx < 64 * 128; idx += 256) {
            int j = idx >> 7, d = idx & 127;
            QsT[d * 65 + j] = Qp[(size_t)j * (NH * HDQ) + d];
        }
    }

    float m[4], l[4], acc[4][8];
    #pragma unroll
    for (int i = 0; i < 4; ++i) { m[i] = -INFINITY; l[i] = 0.f; }
    #pragma unroll
    for (int i = 0; i < 4; ++i)
        #pragma unroll
        for (int j = 0; j < 8; ++j) acc[i][j] = 0.f;

    for (int kt = 0; kt <= qt; ++kt) {
        const float* Kp = K + ((size_t)b * TT + kt * 64) * (NKV * HDQ) + hk * HDQ;
        const float* Vp = V + ((size_t)b * TT + kt * 64) * (NKV * HDQ) + hk * HDQ;
        for (int idx = tid; idx < 64 * 128; idx += 256) {
            int j = idx >> 7, d = idx & 127;
            KsT[d * 65 + j] = Kp[(size_t)j * (NKV * HDQ) + d];
        }
        for (int idx = tid; idx < 64 * 32; idx += 256) {
            int j = idx >> 5, d4 = (idx & 31) << 2;
            float4 vv = *(const float4*)(Vp + (size_t)j * (NKV * HDQ) + d4);
            *(float4*)&Vs[j * 132 + d4] = vv;
        }
        __syncthreads();

        float s[4][4];
        #pragma unroll
        for (int i = 0; i < 4; ++i)
            #pragma unroll
            for (int j = 0; j < 4; ++j) s[i][j] = 0.f;
        #pragma unroll 8
        for (int k = 0; k < 128; ++k) {
            float q[4], kv[4];
            #pragma unroll
            for (int i = 0; i < 4; ++i) q[i]  = QsT[k * 65 + ty * 4 + i];
            #pragma unroll
            for (int j = 0; j < 4; ++j) kv[j] = KsT[k * 65 + j * 16 + tx];
            #pragma unroll
            for (int i = 0; i < 4; ++i)
                #pragma unroll
                for (int j = 0; j < 4; ++j)
                    s[i][j] = fmaf(q[i], kv[j], s[i][j]);
        }
        #pragma unroll
        for (int i = 0; i < 4; ++i)
            #pragma unroll
            for (int j = 0; j < 4; ++j) s[i][j] *= scale;

        if (kt == qt) {
            #pragma unroll
            for (int i = 0; i < 4; ++i) {
                int qi = qBase + ty * 4 + i;
                #pragma unroll
                for (int j = 0; j < 4; ++j)
                    if (kt * 64 + j * 16 + tx > qi) s[i][j] = -1e30f;
            }
        }

        #pragma unroll
        for (int i = 0; i < 4; ++i) {
            float rmax = fmaxf(fmaxf(s[i][0], s[i][1]), fmaxf(s[i][2], s[i][3]));
            #pragma unroll
            for (int off = 8; off; off >>= 1)
                rmax = fmaxf(rmax, __shfl_xor_sync(0xffffffffu, rmax, off));
            float mnew = fmaxf(m[i], rmax);
            float f = __expf(m[i] - mnew);
            m[i] = mnew;
            float rsum = 0.f;
            #pragma unroll
            for (int j = 0; j < 4; ++j) {
                s[i][j] = __expf(s[i][j] - mnew);
                rsum += s[i][j];
            }
            #pragma unroll
            for (int off = 8; off; off >>= 1)
                rsum += __shfl_xor_sync(0xffffffffu, rsum, off);
            l[i] = l[i] * f + rsum;
            #pragma unroll
            for (int j = 0; j < 8; ++j) acc[i][j] *= f;
        }

        #pragma unroll
        for (int i = 0; i < 4; ++i)
            #pragma unroll
            for (int j = 0; j < 4; ++j)
                Ps[(ty * 4 + i) * 65 + j * 16 + tx] = s[i][j];
        __syncthreads();

        #pragma unroll 4
        for (int kk = 0; kk < 64; ++kk) {
            float p[4], v[8];
            #pragma unroll
            for (int i = 0; i < 4; ++i) p[i] = Ps[(ty * 4 + i) * 65 + kk];
            #pragma unroll
            for (int j = 0; j < 8; ++j) v[j] = Vs[kk * 132 + j * 16 + tx];
            #pragma unroll
            for (int i = 0; i < 4; ++i)
                #pragma unroll
                for (int j = 0; j < 8; ++j)
                    acc[i][j] = fmaf(p[i], v[j], acc[i][j]);
        }
        __syncthreads();
    }

    #pragma unroll
    for (int i = 0; i < 4; ++i) {
        float invl = 1.f / l[i];
        float* Op = O + ((size_t)b * TT + qBase + ty * 4 + i) * (NH * HDQ) + h * HDQ;
        #pragma unroll
        for (int j = 0; j < 8; ++j)
            Op[j * 16 + tx] = acc[i][j] * invl;
    }
}

// ---------------- launcher ---------------------------------------------------
extern "C" void kernel_launch(void* const* d_in, const int* in_sizes, int n_in,
                              void* d_out, int out_size)
{
    const float* x  = (const float*)d_in[0];
    const float* wq = (const float*)d_in[1];
    const float* wk = (const float*)d_in[2];
    const float* wv = (const float*)d_in[3];
    const float* wo = (const float*)d_in[4];
    float* out = (float*)d_out;

    float *Qb, *Kb, *Vb, *Ab;
    __nv_bfloat16 *xbf, *abf, *wqt, *wkt, *wvt, *wot;
    cudaGetSymbolAddress((void**)&Qb, g_Q);
    cudaGetSymbolAddress((void**)&Kb, g_K);
    cudaGetSymbolAddress((void**)&Vb, g_V);
    cudaGetSymbolAddress((void**)&Ab, g_A);
    cudaGetSymbolAddress((void**)&xbf, g_xbf);
    cudaGetSymbolAddress((void**)&abf, g_abf);
    cudaGetSymbolAddress((void**)&wqt, g_wqt);
    cudaGetSymbolAddress((void**)&wkt, g_wkt);
    cudaGetSymbolAddress((void**)&wvt, g_wvt);
    cudaGetSymbolAddress((void**)&wot, g_wot);

    cudaFuncSetAttribute(attn_kernel,
                         cudaFuncAttributeMaxDynamicSharedMemorySize, (int)AT_SMEM_BYTES);

    // RoPE table + input conversions
    rope_table_kernel<<<(TT * 64 + 255) / 256, 256>>>();
    split_kernel<<<(BT * KDIM + 255) / 256, 256>>>(x, xbf);
    tsplit_kernel<<<dim3(2048 / 32, KDIM / 32), 256>>>(wq, wqt, 2048);
    tsplit_kernel<<<dim3(512 / 32,  KDIM / 32), 256>>>(wk, wkt, 512);
    tsplit_kernel<<<dim3(512 / 32,  KDIM / 32), 256>>>(wv, wvt, 512);
    tsplit_kernel<<<dim3(2048 / 32, KDIM / 32), 256>>>(wo, wot, 2048);

    // QKV projections (bf16x3 tensor-core GEMM)
    gemm3_kernel<<<dim3(2048 / 128, BT / 128), 256>>>(xbf, wqt, Qb, 2048, KDIM);
    gemm3_kernel<<<dim3(512 / 128,  BT / 128), 256>>>(xbf, wkt, Kb, 512, KDIM);
    gemm3_kernel<<<dim3(512 / 128,  BT / 128), 256>>>(xbf, wvt, Vb, 512, KDIM);

    // RoPE
    rope_kernel<<<(BT * 1024 + 255) / 256, 256>>>(Qb, 2048);
    rope_kernel<<<(BT * 256 + 255) / 256, 256>>>(Kb, 512);

    // Flash attention (fp32 SIMT)
    attn_kernel<<<dim3(TT / 64, NH, BB), 256, AT_SMEM_BYTES>>>(Qb, Kb, Vb, Ab);

    // Output projection
    split_kernel<<<(BT * KDIM + 255) / 256, 256>>>(Ab, abf);
    gemm3_kernel<<<dim3(2048 / 128, BT / 128), 256>>>(abf, wot, out, 2048, KDIM);
}

// round 6
// speedup vs baseline: 3.0257x; 1.6995x over previous
#include <cuda_runtime.h>
#include <cuda_bf16.h>
#include <math.h>
#include <stdint.h>

#define BB   2
#define TT   2048
#define DD   2048
#define NH   16
#define NKV  4
#define HDQ  128
#define BT   4096   // BB*TT
#define KDIM 2048

// ---------------- scratch (static device globals: no allocs allowed) --------
__device__ float g_Q[(size_t)BT * (NH * HDQ)];
__device__ float g_K[(size_t)BT * (NKV * HDQ)];
__device__ float g_V[(size_t)BT * (NKV * HDQ)];

__device__ __nv_bfloat16 g_xbf[(size_t)BT * 2 * KDIM];       // x split  [M][2K]
__device__ __nv_bfloat16 g_abf[(size_t)BT * 2 * KDIM];       // attn-out split
__device__ __nv_bfloat16 g_wqt[(size_t)2048 * 2 * KDIM];     // [N][2K]
__device__ __nv_bfloat16 g_wkt[(size_t)512  * 2 * KDIM];
__device__ __nv_bfloat16 g_wvt[(size_t)512  * 2 * KDIM];
__device__ __nv_bfloat16 g_wot[(size_t)2048 * 2 * KDIM];
__device__ float g_rcos[TT * 64];
__device__ float g_rsin[TT * 64];

// attention operands, bf16 hi/lo
__device__ __nv_bfloat16 g_Qh[(size_t)BT * 2048];
__device__ __nv_bfloat16 g_Ql[(size_t)BT * 2048];
__device__ __nv_bfloat16 g_Kh[(size_t)BT * 512];
__device__ __nv_bfloat16 g_Kl[(size_t)BT * 512];
__device__ __nv_bfloat16 g_Vh[(size_t)BT * 512];
__device__ __nv_bfloat16 g_Vl[(size_t)BT * 512];

// ---------------- helpers ----------------------------------------------------
__device__ __forceinline__ uint32_t smem_u32(const void* p) {
    uint32_t a;
    asm("{ .reg .u64 t; cvta.to.shared.u64 t, %1; cvt.u32.u64 %0, t; }"
        : "=r"(a) : "l"(p));
    return a;
}
__device__ __forceinline__ void ldm_x4(uint32_t& r0, uint32_t& r1,
                                       uint32_t& r2, uint32_t& r3, uint32_t addr) {
    asm volatile("ldmatrix.sync.aligned.m8n8.x4.shared.b16 {%0,%1,%2,%3}, [%4];"
                 : "=r"(r0), "=r"(r1), "=r"(r2), "=r"(r3) : "r"(addr));
}
__device__ __forceinline__ void ldm_x4t(uint32_t& r0, uint32_t& r1,
                                        uint32_t& r2, uint32_t& r3, uint32_t addr) {
    asm volatile("ldmatrix.sync.aligned.m8n8.x4.trans.shared.b16 {%0,%1,%2,%3}, [%4];"
                 : "=r"(r0), "=r"(r1), "=r"(r2), "=r"(r3) : "r"(addr));
}
__device__ __forceinline__ void mma16816(float* d, const uint32_t* a, const uint32_t* b) {
    asm volatile("mma.sync.aligned.m16n8k16.row.col.f32.bf16.bf16.f32 "
                 "{%0,%1,%2,%3}, {%4,%5,%6,%7}, {%8,%9}, {%0,%1,%2,%3};"
                 : "+f"(d[0]), "+f"(d[1]), "+f"(d[2]), "+f"(d[3])
                 : "r"(a[0]), "r"(a[1]), "r"(a[2]), "r"(a[3]),
                   "r"(b[0]), "r"(b[1]));
}
// split pair (a,b) into packed bf16x2 hi and lo
__device__ __forceinline__ void split2(float a, float b, uint32_t& hi, uint32_t& lo) {
    __nv_bfloat16 ha = __float2bfloat16(a), hb = __float2bfloat16(b);
    __nv_bfloat16 la = __float2bfloat16(a - __bfloat162float(ha));
    __nv_bfloat16 lb = __float2bfloat16(b - __bfloat162float(hb));
    __nv_bfloat162 th = __halves2bfloat162(ha, hb);
    __nv_bfloat162 tl = __halves2bfloat162(la, lb);
    hi = *reinterpret_cast<uint32_t*>(&th);
    lo = *reinterpret_cast<uint32_t*>(&tl);
}

// ---------------- conversion kernels ----------------------------------------
__global__ void split_kernel(const float* __restrict__ A, __nv_bfloat16* __restrict__ O)
{
    int idx = blockIdx.x * blockDim.x + threadIdx.x;
    if (idx >= BT * KDIM) return;
    int m = idx >> 11, k = idx & 2047;
    float a = A[idx];
    __nv_bfloat16 h = __float2bfloat16(a);
    __nv_bfloat16 l = __float2bfloat16(a - __bfloat162float(h));
    size_t base = (size_t)m * (2 * KDIM);
    O[base + k] = h;
    O[base + KDIM + k] = l;
}
__global__ void tsplit_kernel(const float* __restrict__ W, __nv_bfloat16* __restrict__ Wt, int N)
{
    __shared__ float tile[32][33];
    int tx = threadIdx.x & 31, ty = threadIdx.x >> 5;
    int nb = blockIdx.x * 32, kb = blockIdx.y * 32;
    #pragma unroll
    for (int r = 0; r < 4; ++r)
        tile[ty + r * 8][tx] = W[(size_t)(kb + ty + r * 8) * N + nb + tx];
    __syncthreads();
    #pragma unroll
    for (int r = 0; r < 4; ++r) {
        int n = nb + ty + r * 8;
        float a = tile[tx][ty + r * 8];
        __nv_bfloat16 h = __float2bfloat16(a);
        __nv_bfloat16 l = __float2bfloat16(a - __bfloat162float(h));
        size_t base = (size_t)n * (2 * KDIM) + kb + tx;
        Wt[base] = h;
        Wt[base + KDIM] = l;
    }
}
// plain split (V): fp32 -> hi/lo bf16, same layout
__global__ void split_plain_kernel(const float* __restrict__ A,
                                   __nv_bfloat16* __restrict__ H,
                                   __nv_bfloat16* __restrict__ L, int n)
{
    int idx = blockIdx.x * blockDim.x + threadIdx.x;
    if (idx >= n) return;
    float a = A[idx];
    __nv_bfloat16 h = __float2bfloat16(a);
    H[idx] = h;
    L[idx] = __float2bfloat16(a - __bfloat162float(h));
}

// ---------------- bf16x3 GEMM via mma.sync -----------------------------------
__global__ __launch_bounds__(256, 2) void gemm3_kernel(
    const __nv_bfloat16* __restrict__ A, const __nv_bfloat16* __restrict__ Bt,
    float* __restrict__ C, int N, int K)
{
    __shared__ __nv_bfloat16 As[2][128][40];
    __shared__ __nv_bfloat16 Bs[2][128][40];

    const int tid = threadIdx.x;
    const int lane = tid & 31, wid = tid >> 5;
    const int wm = wid & 3, wn = wid >> 2;
    const int mBase = blockIdx.y << 7, nBase = blockIdx.x << 7;
    const int twoK = 2 * K;
    const int KC = K >> 5;
    const int NC = 3 * KC;

    const int lrow = tid >> 1;
    const int lseg = (tid & 1) << 4;
    const int ldRow = lane & 15;
    const int ldCol = (lane >> 4) << 3;

    float acc[2][8][4];
    #pragma unroll
    for (int i = 0; i < 2; ++i)
        #pragma unroll
        for (int j = 0; j < 8; ++j)
            #pragma unroll
            for (int r = 0; r < 4; ++r) acc[i][j][r] = 0.f;

    {
        const __nv_bfloat16* ga = A  + (size_t)(mBase + lrow) * twoK + lseg;
        const __nv_bfloat16* gb = Bt + (size_t)(nBase + lrow) * twoK + lseg;
        *(uint4*)&As[0][lrow][lseg]     = *(const uint4*)ga;
        *(uint4*)&As[0][lrow][lseg + 8] = *(const uint4*)(ga + 8);
        *(uint4*)&Bs[0][lrow][lseg]     = *(const uint4*)gb;
        *(uint4*)&Bs[0][lrow][lseg + 8] = *(const uint4*)(gb + 8);
    }
    __syncthreads();

    for (int c = 0; c < NC; ++c) {
        const int b = c & 1;
        uint4 ra0, ra1, rb0, rb1;
        const bool pf = (c + 1 < NC);
        if (pf) {
            int cn = c + 1;
            int p = cn / KC, kc = cn - p * KC;
            int aoff = kc * 32 + (p == 2 ? K : 0);
            int boff = kc * 32 + (p == 1 ? K : 0);
            const __nv_bfloat16* ga = A  + (size_t)(mBase + lrow) * twoK + aoff + lseg;
            const __nv_bfloat16* gb = Bt + (size_t)(nBase + lrow) * twoK + boff + lseg;
            ra0 = *(const uint4*)ga; ra1 = *(const uint4*)(ga + 8);
            rb0 = *(const uint4*)gb; rb1 = *(const uint4*)(gb + 8);
        }

        const uint32_t sA = smem_u32(&As[b][0][0]);
        const uint32_t sB = smem_u32(&Bs[b][0][0]);
        #pragma unroll
        for (int ks = 0; ks < 2; ++ks) {
            uint32_t af[2][4], bfr[8][2];
            #pragma unroll
            for (int mf = 0; mf < 2; ++mf) {
                uint32_t addr = sA + ((wm * 32 + mf * 16 + ldRow) * 40
                                      + ks * 16 + ldCol) * 2;
                ldm_x4(af[mf][0], af[mf][1], af[mf][2], af[mf][3], addr);
            }
            #pragma unroll
            for (int ng = 0; ng < 4; ++ng) {
                uint32_t r0, r1, r2, r3;
                uint32_t addr = sB + ((wn * 64 + ng * 16 + ldRow) * 40
                                      + ks * 16 + ldCol) * 2;
                ldm_x4(r0, r1, r2, r3, addr);
                bfr[ng * 2 + 0][0] = r0; bfr[ng * 2 + 1][0] = r1;
                bfr[ng * 2 + 0][1] = r2; bfr[ng * 2 + 1][1] = r3;
            }
            #pragma unroll
            for (int mf = 0; mf < 2; ++mf)
                #pragma unroll
                for (int nf = 0; nf < 8; ++nf)
                    mma16816(acc[mf][nf], af[mf], bfr[nf]);
        }

        if (pf) {
            const int nb = b ^ 1;
            *(uint4*)&As[nb][lrow][lseg]     = ra0;
            *(uint4*)&As[nb][lrow][lseg + 8] = ra1;
            *(uint4*)&Bs[nb][lrow][lseg]     = rb0;
            *(uint4*)&Bs[nb][lrow][lseg + 8] = rb1;
        }
        __syncthreads();
    }

    const int gid = lane >> 2, tig = lane & 3;
    #pragma unroll
    for (int mf = 0; mf < 2; ++mf) {
        #pragma unroll
        for (int nf = 0; nf < 8; ++nf) {
            int row = mBase + wm * 32 + mf * 16 + gid;
            int col = nBase + wn * 64 + nf * 8 + tig * 2;
            float2 v0 = make_float2(acc[mf][nf][0], acc[mf][nf][1]);
            float2 v1 = make_float2(acc[mf][nf][2], acc[mf][nf][3]);
            *(float2*)&C[(size_t)row * N + col] = v0;
            *(float2*)&C[(size_t)(row + 8) * N + col] = v1;
        }
    }
}

// ---------------- RoPE table, rope+split -------------------------------------
__global__ void rope_table_kernel()
{
    int idx = blockIdx.x * blockDim.x + threadIdx.x;
    if (idx >= TT * 64) return;
    int t = idx >> 6, d = idx & 63;
    double inv = exp2(-(double)d * (19.931568569324174 / 64.0));
    double ang = (double)t * inv;
    g_rcos[idx] = (float)cos(ang);
    g_rsin[idx] = (float)sin(ang);
}
// rope + optional scale + hi/lo split.  cols = n_heads*128
__global__ void rope_split_kernel(const float* __restrict__ in,
                                  __nv_bfloat16* __restrict__ H,
                                  __nv_bfloat16* __restrict__ L,
                                  int cols, float scale)
{
    int idx = blockIdx.x * blockDim.x + threadIdx.x;
    int ppr = cols >> 1;
    if (idx >= BT * ppr) return;
    int row = idx / ppr;
    int p = idx - row * ppr;
    int h = p >> 6, d = p & 63;
    int t = row & (TT - 1);
    size_t base = (size_t)row * cols + h * 128 + d;
    float u1 = in[base];
    float u2 = in[base + 64];
    float c = g_rcos[t * 64 + d];
    float s = g_rsin[t * 64 + d];
    float o1 = (u1 * c - u2 * s) * scale;
    float o2 = (u2 * c + u1 * s) * scale;
    __nv_bfloat16 h1 = __float2bfloat16(o1);
    __nv_bfloat16 h2 = __float2bfloat16(o2);
    H[base] = h1;
    H[base + 64] = h2;
    L[base] = __float2bfloat16(o1 - __bfloat162float(h1));
    L[base + 64] = __float2bfloat16(o2 - __bfloat162float(h2));
}

// ---------------- tensor-core flash attention --------------------------------
// CTA: 64 q rows, 4 warps (m16 each), BN=64 kv per tile, D=128.
// S = Qh*Kh + Qh*Kl + Ql*Kh; O += Ph*Vh + Ph*Vl + Pl*Vh; fp32 accum.
#define AST 136   // smem row stride in halves (272B: conflict-free ldmatrix)
#define ATT_SMEM (6 * 64 * AST * 2)

__global__ __launch_bounds__(128) void attn_mma_kernel(
    const __nv_bfloat16* __restrict__ Qh, const __nv_bfloat16* __restrict__ Ql,
    const __nv_bfloat16* __restrict__ Kh, const __nv_bfloat16* __restrict__ Kl,
    const __nv_bfloat16* __restrict__ Vh, const __nv_bfloat16* __restrict__ Vl,
    __nv_bfloat16* __restrict__ Oo)
{
    extern __shared__ __nv_bfloat16 smb[];
    __nv_bfloat16* sQh = smb;
    __nv_bfloat16* sQl = sQh + 64 * AST;
    __nv_bfloat16* sKh = sQl + 64 * AST;
    __nv_bfloat16* sKl = sKh + 64 * AST;
    __nv_bfloat16* sVh = sKl + 64 * AST;
    __nv_bfloat16* sVl = sVh + 64 * AST;

    const int tid = threadIdx.x;
    const int lane = tid & 31, wm = tid >> 5;
    const int gid = lane >> 2, tig = lane & 3;
    const int ldRow = lane & 15, ldCol = (lane >> 4) << 3;
    const int qt = gridDim.x - 1 - blockIdx.x;
    const int h = blockIdx.y, b = blockIdx.z;
    const int hk = h >> 2;
    const int qBase = qt * 64;

    // load Q tile hi/lo (gmem row stride 2048 halves)
    {
        const __nv_bfloat16* gqh = Qh + ((size_t)(b * TT + qBase)) * 2048 + h * 128;
        const __nv_bfloat16* gql = Ql + ((size_t)(b * TT + qBase)) * 2048 + h * 128;
        for (int idx = tid; idx < 1024; idx += 128) {
            int r = idx >> 4, c = (idx & 15) << 3;
            *(uint4*)&sQh[r * AST + c] = *(const uint4*)(gqh + (size_t)r * 2048 + c);
            *(uint4*)&sQl[r * AST + c] = *(const uint4*)(gql + (size_t)r * 2048 + c);
        }
    }

    float oacc[16][4];
    #pragma unroll
    for (int i = 0; i < 16; ++i)
        #pragma unroll
        for (int r = 0; r < 4; ++r) oacc[i][r] = 0.f;
    float mrow[2] = {-INFINITY, -INFINITY};
    float lrow[2] = {0.f, 0.f};

    const uint32_t aQh = smem_u32(sQh), aQl = smem_u32(sQl);
    const uint32_t aKh = smem_u32(sKh), aKl = smem_u32(sKl);
    const uint32_t aVh = smem_u32(sVh), aVl = smem_u32(sVl);

    for (int kt = 0; kt <= qt; ++kt) {
        __syncthreads();
        {
            const size_t base = ((size_t)(b * TT + kt * 64)) * 512 + hk * 128;
            for (int idx = tid; idx < 1024; idx += 128) {
                int r = idx >> 4, c = (idx & 15) << 3;
                size_t g = base + (size_t)r * 512 + c;
                int so = r * AST + c;
                *(uint4*)&sKh[so] = *(const uint4*)(Kh + g);
                *(uint4*)&sKl[so] = *(const uint4*)(Kl + g);
                *(uint4*)&sVh[so] = *(const uint4*)(Vh + g);
                *(uint4*)&sVl[so] = *(const uint4*)(Vl + g);
            }
        }
        __syncthreads();

        // ---- S = Q K^T (bf16x3) ----
        float sacc[8][4];
        #pragma unroll
        for (int i = 0; i < 8; ++i)
            #pragma unroll
            for (int r = 0; r < 4; ++r) sacc[i][r] = 0.f;

        #pragma unroll
        for (int ks = 0; ks < 8; ++ks) {
            uint32_t ah[4], al[4];
            uint32_t qoff = ((wm * 16 + ldRow) * AST + ks * 16 + ldCol) * 2;
            ldm_x4(ah[0], ah[1], ah[2], ah[3], aQh + qoff);
            ldm_x4(al[0], al[1], al[2], al[3], aQl + qoff);
            #pragma unroll
            for (int j = 0; j < 4; ++j) {
                uint32_t koff = ((j * 16 + ldRow) * AST + ks * 16 + ldCol) * 2;
                uint32_t r0, r1, r2, r3;
                ldm_x4(r0, r1, r2, r3, aKh + koff);
                uint32_t bh0[2] = {r0, r2}, bh1[2] = {r1, r3};
                mma16816(sacc[2 * j], ah, bh0);
                mma16816(sacc[2 * j + 1], ah, bh1);
                mma16816(sacc[2 * j], al, bh0);
                mma16816(sacc[2 * j + 1], al, bh1);
                ldm_x4(r0, r1, r2, r3, aKl + koff);
                uint32_t bl0[2] = {r0, r2}, bl1[2] = {r1, r3};
                mma16816(sacc[2 * j], ah, bl0);
                mma16816(sacc[2 * j + 1], ah, bl1);
            }
        }

        // ---- causal mask (diagonal tile only) ----
        if (kt == qt) {
            int lr0 = wm * 16 + gid, lr1 = lr0 + 8;
            #pragma unroll
            for (int nb = 0; nb < 8; ++nb) {
                int lc = nb * 8 + tig * 2;
                if (lc > lr0)     sacc[nb][0] = -1e30f;
                if (lc + 1 > lr0) sacc[nb][1] = -1e30f;
                if (lc > lr1)     sacc[nb][2] = -1e30f;
                if (lc + 1 > lr1) sacc[nb][3] = -1e30f;
            }
        }

        // ---- online softmax ----
        #pragma unroll
        for (int hf = 0; hf < 2; ++hf) {
            float rmax = -1e30f;
            #pragma unroll
            for (int nb = 0; nb < 8; ++nb)
                rmax = fmaxf(rmax, fmaxf(sacc[nb][hf * 2], sacc[nb][hf * 2 + 1]));
            rmax = fmaxf(rmax, __shfl_xor_sync(0xffffffffu, rmax, 1));
            rmax = fmaxf(rmax, __shfl_xor_sync(0xffffffffu, rmax, 2));
            float mnew = fmaxf(mrow[hf], rmax);
            float f = __expf(mrow[hf] - mnew);
            mrow[hf] = mnew;
            float rsum = 0.f;
            #pragma unroll
            for (int nb = 0; nb < 8; ++nb) {
                float s0 = __expf(sacc[nb][hf * 2] - mnew);
                float s1 = __expf(sacc[nb][hf * 2 + 1] - mnew);
                sacc[nb][hf * 2] = s0;
                sacc[nb][hf * 2 + 1] = s1;
                rsum += s0 + s1;
            }
            rsum += __shfl_xor_sync(0xffffffffu, rsum, 1);
            rsum += __shfl_xor_sync(0xffffffffu, rsum, 2);
            lrow[hf] = lrow[hf] * f + rsum;
            #pragma unroll
            for (int nb = 0; nb < 16; ++nb) {
                oacc[nb][hf * 2] *= f;
                oacc[nb][hf * 2 + 1] *= f;
            }
        }

        // ---- P -> A-fragments (hi/lo) ----
        uint32_t ph[4][4], pl[4][4];
        #pragma unroll
        for (int ks = 0; ks < 4; ++ks) {
            split2(sacc[2 * ks][0], sacc[2 * ks][1], ph[ks][0], pl[ks][0]);
            split2(sacc[2 * ks][2], sacc[2 * ks][3], ph[ks][1], pl[ks][1]);
            split2(sacc[2 * ks + 1][0], sacc[2 * ks + 1][1], ph[ks][2], pl[ks][2]);
            split2(sacc[2 * ks + 1][2], sacc[2 * ks + 1][3], ph[ks][3], pl[ks][3]);
        }

        // ---- O += P V (bf16x3) ----
        #pragma unroll
        for (int ks = 0; ks < 4; ++ks) {
            #pragma unroll
            for (int j = 0; j < 8; ++j) {
                uint32_t voff = ((ks * 16 + ldRow) * AST + j * 16 + ldCol) * 2;
                uint32_t r0, r1, r2, r3;
                ldm_x4t(r0, r1, r2, r3, aVh + voff);
                uint32_t vh0[2] = {r0, r1}, vh1[2] = {r2, r3};
                mma16816(oacc[2 * j], ph[ks], vh0);
                mma16816(oacc[2 * j + 1], ph[ks], vh1);
                mma16816(oacc[2 * j], pl[ks], vh0);
                mma16816(oacc[2 * j + 1], pl[ks], vh1);
                ldm_x4t(r0, r1, r2, r3, aVl + voff);
                uint32_t vl0[2] = {r0, r1}, vl1[2] = {r2, r3};
                mma16816(oacc[2 * j], ph[ks], vl0);
                mma16816(oacc[2 * j + 1], ph[ks], vl1);
            }
        }
    }

    // ---- epilogue: write hi/lo bf16 directly into abf layout [m][2*2048] ----
    float inv0 = 1.f / lrow[0], inv1 = 1.f / lrow[1];
    size_t row0 = (size_t)(b * TT + qBase + wm * 16 + gid);
    __nv_bfloat16* p0 = Oo + row0 * (2 * KDIM) + h * 128 + tig * 2;
    __nv_bfloat16* p1 = Oo + (row0 + 8) * (2 * KDIM) + h * 128 + tig * 2;
    #pragma unroll
    for (int nb = 0; nb < 16; ++nb) {
        uint32_t hi, lo;
        split2(oacc[nb][0] * inv0, oacc[nb][1] * inv0, hi, lo);
        *(uint32_t*)(p0 + nb * 8) = hi;
        *(uint32_t*)(p0 + KDIM + nb * 8) = lo;
        split2(oacc[nb][2] * inv1, oacc[nb][3] * inv1, hi, lo);
        *(uint32_t*)(p1 + nb * 8) = hi;
        *(uint32_t*)(p1 + KDIM + nb * 8) = lo;
    }
}

// ---------------- launcher ---------------------------------------------------
extern "C" void kernel_launch(void* const* d_in, const int* in_sizes, int n_in,
                              void* d_out, int out_size)
{
    const float* x  = (const float*)d_in[0];
    const float* wq = (const float*)d_in[1];
    const float* wk = (const float*)d_in[2];
    const float* wv = (const float*)d_in[3];
    const float* wo = (const float*)d_in[4];
    float* out = (float*)d_out;

    float *Qb, *Kb, *Vb;
    __nv_bfloat16 *xbf, *abf, *wqt, *wkt, *wvt, *wot;
    __nv_bfloat16 *qh, *ql, *kh, *kl, *vh, *vl;
    cudaGetSymbolAddress((void**)&Qb, g_Q);
    cudaGetSymbolAddress((void**)&Kb, g_K);
    cudaGetSymbolAddress((void**)&Vb, g_V);
    cudaGetSymbolAddress((void**)&xbf, g_xbf);
    cudaGetSymbolAddress((void**)&abf, g_abf);
    cudaGetSymbolAddress((void**)&wqt, g_wqt);
    cudaGetSymbolAddress((void**)&wkt, g_wkt);
    cudaGetSymbolAddress((void**)&wvt, g_wvt);
    cudaGetSymbolAddress((void**)&wot, g_wot);
    cudaGetSymbolAddress((void**)&qh, g_Qh);
    cudaGetSymbolAddress((void**)&ql, g_Ql);
    cudaGetSymbolAddress((void**)&kh, g_Kh);
    cudaGetSymbolAddress((void**)&kl, g_Kl);
    cudaGetSymbolAddress((void**)&vh, g_Vh);
    cudaGetSymbolAddress((void**)&vl, g_Vl);

    cudaFuncSetAttribute(attn_mma_kernel,
                         cudaFuncAttributeMaxDynamicSharedMemorySize, ATT_SMEM);

    // RoPE table + input conversions
    rope_table_kernel<<<(TT * 64 + 255) / 256, 256>>>();
    split_kernel<<<(BT * KDIM + 255) / 256, 256>>>(x, xbf);
    tsplit_kernel<<<dim3(2048 / 32, KDIM / 32), 256>>>(wq, wqt, 2048);
    tsplit_kernel<<<dim3(512 / 32,  KDIM / 32), 256>>>(wk, wkt, 512);
    tsplit_kernel<<<dim3(512 / 32,  KDIM / 32), 256>>>(wv, wvt, 512);
    tsplit_kernel<<<dim3(2048 / 32, KDIM / 32), 256>>>(wo, wot, 2048);

    // QKV projections (bf16x3 tensor-core GEMM)
    gemm3_kernel<<<dim3(2048 / 128, BT / 128), 256>>>(xbf, wqt, Qb, 2048, KDIM);
    gemm3_kernel<<<dim3(512 / 128,  BT / 128), 256>>>(xbf, wkt, Kb, 512, KDIM);
    gemm3_kernel<<<dim3(512 / 128,  BT / 128), 256>>>(xbf, wvt, Vb, 512, KDIM);

    // RoPE + hi/lo split (Q pre-scaled by 1/sqrt(128)); V plain split
    rope_split_kernel<<<(BT * 1024 + 255) / 256, 256>>>(Qb, qh, ql, 2048,
                                                        0.08838834764831845f);
    rope_split_kernel<<<(BT * 256 + 255) / 256, 256>>>(Kb, kh, kl, 512, 1.0f);
    split_plain_kernel<<<(BT * 512 + 255) / 256, 256>>>(Vb, vh, vl, BT * 512);

    // tensor-core flash attention -> abf (hi/lo)
    attn_mma_kernel<<<dim3(TT / 64, NH, BB), 128, ATT_SMEM>>>(qh, ql, kh, kl,
                                                              vh, vl, abf);

    // Output projection
    gemm3_kernel<<<dim3(2048 / 128, BT / 128), 256>>>(abf, wot, out, 2048, KDIM);
}

// round 7
// speedup vs baseline: 3.1237x; 1.0324x over previous
#include <cuda_runtime.h>
#include <cuda_bf16.h>
#include <math.h>
#include <stdint.h>

#define BB   2
#define TT   2048
#define DD   2048
#define NH   16
#define NKV  4
#define HDQ  128
#define BT   4096   // BB*TT
#define KDIM 2048

// ---------------- scratch (static device globals: no allocs allowed) --------
__device__ float g_Q[(size_t)BT * (NH * HDQ)];
__device__ float g_K[(size_t)BT * (NKV * HDQ)];
__device__ float g_V[(size_t)BT * (NKV * HDQ)];

__device__ __nv_bfloat16 g_xbf[(size_t)BT * 2 * KDIM];       // x split  [M][2K]
__device__ __nv_bfloat16 g_abf[(size_t)BT * 2 * KDIM];       // attn-out split
__device__ __nv_bfloat16 g_wqt[(size_t)2048 * 2 * KDIM];     // [N][2K]
__device__ __nv_bfloat16 g_wkt[(size_t)512  * 2 * KDIM];
__device__ __nv_bfloat16 g_wvt[(size_t)512  * 2 * KDIM];
__device__ __nv_bfloat16 g_wot[(size_t)2048 * 2 * KDIM];
__device__ float g_rcos[TT * 64];
__device__ float g_rsin[TT * 64];

// attention operands, bf16 hi/lo
__device__ __nv_bfloat16 g_Qh[(size_t)BT * 2048];
__device__ __nv_bfloat16 g_Ql[(size_t)BT * 2048];
__device__ __nv_bfloat16 g_Kh[(size_t)BT * 512];
__device__ __nv_bfloat16 g_Kl[(size_t)BT * 512];
__device__ __nv_bfloat16 g_Vh[(size_t)BT * 512];
__device__ __nv_bfloat16 g_Vl[(size_t)BT * 512];

// ---------------- helpers ----------------------------------------------------
__device__ __forceinline__ uint32_t smem_u32(const void* p) {
    uint32_t a;
    asm("{ .reg .u64 t; cvta.to.shared.u64 t, %1; cvt.u32.u64 %0, t; }"
        : "=r"(a) : "l"(p));
    return a;
}
__device__ __forceinline__ void ldm_x4(uint32_t& r0, uint32_t& r1,
                                       uint32_t& r2, uint32_t& r3, uint32_t addr) {
    asm volatile("ldmatrix.sync.aligned.m8n8.x4.shared.b16 {%0,%1,%2,%3}, [%4];"
                 : "=r"(r0), "=r"(r1), "=r"(r2), "=r"(r3) : "r"(addr));
}
__device__ __forceinline__ void ldm_x4t(uint32_t& r0, uint32_t& r1,
                                        uint32_t& r2, uint32_t& r3, uint32_t addr) {
    asm volatile("ldmatrix.sync.aligned.m8n8.x4.trans.shared.b16 {%0,%1,%2,%3}, [%4];"
                 : "=r"(r0), "=r"(r1), "=r"(r2), "=r"(r3) : "r"(addr));
}
__device__ __forceinline__ void mma16816(float* d, const uint32_t* a, const uint32_t* b) {
    asm volatile("mma.sync.aligned.m16n8k16.row.col.f32.bf16.bf16.f32 "
                 "{%0,%1,%2,%3}, {%4,%5,%6,%7}, {%8,%9}, {%0,%1,%2,%3};"
                 : "+f"(d[0]), "+f"(d[1]), "+f"(d[2]), "+f"(d[3])
                 : "r"(a[0]), "r"(a[1]), "r"(a[2]), "r"(a[3]),
                   "r"(b[0]), "r"(b[1]));
}
__device__ __forceinline__ void cp_async16(uint32_t saddr, const void* gaddr) {
    asm volatile("cp.async.cg.shared.global [%0], [%1], 16;"
                 :: "r"(saddr), "l"(gaddr) : "memory");
}
#define CP_COMMIT() asm volatile("cp.async.commit_group;" ::: "memory")
#define CP_WAIT1()  asm volatile("cp.async.wait_group 1;" ::: "memory")
#define CP_WAIT0()  asm volatile("cp.async.wait_group 0;" ::: "memory")

// split pair (a,b) into packed bf16x2 hi and lo
__device__ __forceinline__ void split2(float a, float b, uint32_t& hi, uint32_t& lo) {
    __nv_bfloat16 ha = __float2bfloat16(a), hb = __float2bfloat16(b);
    __nv_bfloat16 la = __float2bfloat16(a - __bfloat162float(ha));
    __nv_bfloat16 lb = __float2bfloat16(b - __bfloat162float(hb));
    __nv_bfloat162 th = __halves2bfloat162(ha, hb);
    __nv_bfloat162 tl = __halves2bfloat162(la, lb);
    hi = *reinterpret_cast<uint32_t*>(&th);
    lo = *reinterpret_cast<uint32_t*>(&tl);
}

// ---------------- conversion kernels ----------------------------------------
__global__ void split_kernel(const float* __restrict__ A, __nv_bfloat16* __restrict__ O)
{
    int idx = blockIdx.x * blockDim.x + threadIdx.x;
    if (idx >= BT * KDIM) return;
    int m = idx >> 11, k = idx & 2047;
    float a = A[idx];
    __nv_bfloat16 h = __float2bfloat16(a);
    __nv_bfloat16 l = __float2bfloat16(a - __bfloat162float(h));
    size_t base = (size_t)m * (2 * KDIM);
    O[base + k] = h;
    O[base + KDIM + k] = l;
}
__global__ void tsplit_kernel(const float* __restrict__ W, __nv_bfloat16* __restrict__ Wt, int N)
{
    __shared__ float tile[32][33];
    int tx = threadIdx.x & 31, ty = threadIdx.x >> 5;
    int nb = blockIdx.x * 32, kb = blockIdx.y * 32;
    #pragma unroll
    for (int r = 0; r < 4; ++r)
        tile[ty + r * 8][tx] = W[(size_t)(kb + ty + r * 8) * N + nb + tx];
    __syncthreads();
    #pragma unroll
    for (int r = 0; r < 4; ++r) {
        int n = nb + ty + r * 8;
        float a = tile[tx][ty + r * 8];
        __nv_bfloat16 h = __float2bfloat16(a);
        __nv_bfloat16 l = __float2bfloat16(a - __bfloat162float(h));
        size_t base = (size_t)n * (2 * KDIM) + kb + tx;
        Wt[base] = h;
        Wt[base + KDIM] = l;
    }
}
__global__ void split_plain_kernel(const float* __restrict__ A,
                                   __nv_bfloat16* __restrict__ H,
                                   __nv_bfloat16* __restrict__ L, int n)
{
    int idx = blockIdx.x * blockDim.x + threadIdx.x;
    if (idx >= n) return;
    float a = A[idx];
    __nv_bfloat16 h = __float2bfloat16(a);
    H[idx] = h;
    L[idx] = __float2bfloat16(a - __bfloat162float(h));
}

// ---------------- bf16x3 GEMM via mma.sync + cp.async 3-stage pipeline -------
// C[M,N] = A[M,2K](hi|lo) @ Bt[N,2K](hi|lo)^T over passes hi*hi + hi*lo + lo*hi.
// 128x128x32 tile, 256 threads, 8 warps (4m x 2n), warp tile 32x64.
// Dynamic smem: 3 stages x (A 128x40 + B 128x40) halves = 61440 bytes.
#define GSTAGE_H   (128 * 40)              // halves per matrix per stage
#define G_SMEM_B   (6 * GSTAGE_H * 2)      // 61440 bytes

__global__ __launch_bounds__(256, 2) void gemm3_kernel(
    const __nv_bfloat16* __restrict__ A, const __nv_bfloat16* __restrict__ Bt,
    float* __restrict__ C, int N, int K)
{
    extern __shared__ __nv_bfloat16 gsm[];
    const uint32_t smb = smem_u32(gsm);

    const int tid = threadIdx.x;
    const int lane = tid & 31, wid = tid >> 5;
    const int wm = wid & 3, wn = wid >> 2;
    const int mBase = blockIdx.y << 7, nBase = blockIdx.x << 7;
    const int twoK = 2 * K;
    const int KC = K >> 5;
    const int NC = 3 * KC;

    const int lrow = tid >> 1;
    const int lseg = (tid & 1) << 4;
    const int ldRow = lane & 15;
    const int ldCol = (lane >> 4) << 3;

    // per-thread gmem/smem bases for the loader
    const __nv_bfloat16* gA = A  + (size_t)(mBase + lrow) * twoK + lseg;
    const __nv_bfloat16* gB = Bt + (size_t)(nBase + lrow) * twoK + lseg;
    const uint32_t sOff = (uint32_t)(lrow * 40 + lseg) * 2;

    float acc[2][8][4];
    #pragma unroll
    for (int i = 0; i < 2; ++i)
        #pragma unroll
        for (int j = 0; j < 8; ++j)
            #pragma unroll
            for (int r = 0; r < 4; ++r) acc[i][j][r] = 0.f;

    // issue chunk c into stage s
    auto issue = [&](int c, int s) {
        int p = c / KC, kc = c - p * KC;
        int aoff = kc * 32 + (p == 2 ? K : 0);
        int boff = kc * 32 + (p == 1 ? K : 0);
        const __nv_bfloat16* ga = gA + aoff;
        const __nv_bfloat16* gb = gB + boff;
        uint32_t sa = smb + (uint32_t)s * (GSTAGE_H * 2) + sOff;
        uint32_t sb = smb + (uint32_t)(3 * GSTAGE_H * 2) + (uint32_t)s * (GSTAGE_H * 2) + sOff;
        cp_async16(sa,      ga);
        cp_async16(sa + 16, ga + 8);
        cp_async16(sb,      gb);
        cp_async16(sb + 16, gb + 8);
        CP_COMMIT();
    };

    issue(0, 0);
    issue(1, 1);

    int stage = 0;
    for (int c = 0; c < NC; ++c) {
        if (c + 1 < NC) CP_WAIT1(); else CP_WAIT0();
        __syncthreads();
        if (c + 2 < NC) {
            int ns = stage + 2; if (ns >= 3) ns -= 3;
            issue(c + 2, ns);
        }

        const uint32_t sA = smb + (uint32_t)stage * (GSTAGE_H * 2);
        const uint32_t sB = smb + (uint32_t)(3 * GSTAGE_H * 2) + (uint32_t)stage * (GSTAGE_H * 2);
        #pragma unroll
        for (int ks = 0; ks < 2; ++ks) {
            uint32_t af[2][4], bfr[8][2];
            #pragma unroll
            for (int mf = 0; mf < 2; ++mf) {
                uint32_t addr = sA + ((wm * 32 + mf * 16 + ldRow) * 40
                                      + ks * 16 + ldCol) * 2;
                ldm_x4(af[mf][0], af[mf][1], af[mf][2], af[mf][3], addr);
            }
            #pragma unroll
            for (int ng = 0; ng < 4; ++ng) {
                uint32_t r0, r1, r2, r3;
                uint32_t addr = sB + ((wn * 64 + ng * 16 + ldRow) * 40
                                      + ks * 16 + ldCol) * 2;
                ldm_x4(r0, r1, r2, r3, addr);
                bfr[ng * 2 + 0][0] = r0; bfr[ng * 2 + 1][0] = r1;
                bfr[ng * 2 + 0][1] = r2; bfr[ng * 2 + 1][1] = r3;
            }
            #pragma unroll
            for (int mf = 0; mf < 2; ++mf)
                #pragma unroll
                for (int nf = 0; nf < 8; ++nf)
                    mma16816(acc[mf][nf], af[mf], bfr[nf]);
        }
        ++stage; if (stage == 3) stage = 0;
        __syncthreads();
    }

    const int gid = lane >> 2, tig = lane & 3;
    #pragma unroll
    for (int mf = 0; mf < 2; ++mf) {
        #pragma unroll
        for (int nf = 0; nf < 8; ++nf) {
            int row = mBase + wm * 32 + mf * 16 + gid;
            int col = nBase + wn * 64 + nf * 8 + tig * 2;
            float2 v0 = make_float2(acc[mf][nf][0], acc[mf][nf][1]);
            float2 v1 = make_float2(acc[mf][nf][2], acc[mf][nf][3]);
            *(float2*)&C[(size_t)row * N + col] = v0;
            *(float2*)&C[(size_t)(row + 8) * N + col] = v1;
        }
    }
}

// ---------------- RoPE table, rope+split -------------------------------------
__global__ void rope_table_kernel()
{
    int idx = blockIdx.x * blockDim.x + threadIdx.x;
    if (idx >= TT * 64) return;
    int t = idx >> 6, d = idx & 63;
    double inv = exp2(-(double)d * (19.931568569324174 / 64.0));
    double ang = (double)t * inv;
    g_rcos[idx] = (float)cos(ang);
    g_rsin[idx] = (float)sin(ang);
}
__global__ void rope_split_kernel(const float* __restrict__ in,
                                  __nv_bfloat16* __restrict__ H,
                                  __nv_bfloat16* __restrict__ L,
                                  int cols, float scale)
{
    int idx = blockIdx.x * blockDim.x + threadIdx.x;
    int ppr = cols >> 1;
    if (idx >= BT * ppr) return;
    int row = idx / ppr;
    int p = idx - row * ppr;
    int h = p >> 6, d = p & 63;
    int t = row & (TT - 1);
    size_t base = (size_t)row * cols + h * 128 + d;
    float u1 = in[base];
    float u2 = in[base + 64];
    float c = g_rcos[t * 64 + d];
    float s = g_rsin[t * 64 + d];
    float o1 = (u1 * c - u2 * s) * scale;
    float o2 = (u2 * c + u1 * s) * scale;
    __nv_bfloat16 h1 = __float2bfloat16(o1);
    __nv_bfloat16 h2 = __float2bfloat16(o2);
    H[base] = h1;
    H[base + 64] = h2;
    L[base] = __float2bfloat16(o1 - __bfloat162float(h1));
    L[base + 64] = __float2bfloat16(o2 - __bfloat162float(h2));
}

// ---------------- tensor-core flash attention --------------------------------
#define AST 136
#define ATT_SMEM (6 * 64 * AST * 2)

__global__ __launch_bounds__(128) void attn_mma_kernel(
    const __nv_bfloat16* __restrict__ Qh, const __nv_bfloat16* __restrict__ Ql,
    const __nv_bfloat16* __restrict__ Kh, const __nv_bfloat16* __restrict__ Kl,
    const __nv_bfloat16* __restrict__ Vh, const __nv_bfloat16* __restrict__ Vl,
    __nv_bfloat16* __restrict__ Oo)
{
    extern __shared__ __nv_bfloat16 smb[];
    __nv_bfloat16* sQh = smb;
    __nv_bfloat16* sQl = sQh + 64 * AST;
    __nv_bfloat16* sKh = sQl + 64 * AST;
    __nv_bfloat16* sKl = sKh + 64 * AST;
    __nv_bfloat16* sVh = sKl + 64 * AST;
    __nv_bfloat16* sVl = sVh + 64 * AST;

    const int tid = threadIdx.x;
    const int lane = tid & 31, wm = tid >> 5;
    const int gid = lane >> 2, tig = lane & 3;
    const int ldRow = lane & 15, ldCol = (lane >> 4) << 3;
    const int qt = gridDim.x - 1 - blockIdx.x;
    const int h = blockIdx.y, b = blockIdx.z;
    const int hk = h >> 2;
    const int qBase = qt * 64;

    {
        const __nv_bfloat16* gqh = Qh + ((size_t)(b * TT + qBase)) * 2048 + h * 128;
        const __nv_bfloat16* gql = Ql + ((size_t)(b * TT + qBase)) * 2048 + h * 128;
        for (int idx = tid; idx < 1024; idx += 128) {
            int r = idx >> 4, c = (idx & 15) << 3;
            *(uint4*)&sQh[r * AST + c] = *(const uint4*)(gqh + (size_t)r * 2048 + c);
            *(uint4*)&sQl[r * AST + c] = *(const uint4*)(gql + (size_t)r * 2048 + c);
        }
    }

    float oacc[16][4];
    #pragma unroll
    for (int i = 0; i < 16; ++i)
        #pragma unroll
        for (int r = 0; r < 4; ++r) oacc[i][r] = 0.f;
    float mrow[2] = {-INFINITY, -INFINITY};
    float lrow[2] = {0.f, 0.f};

    const uint32_t aQh = smem_u32(sQh), aQl = smem_u32(sQl);
    const uint32_t aKh = smem_u32(sKh), aKl = smem_u32(sKl);
    const uint32_t aVh = smem_u32(sVh), aVl = smem_u32(sVl);

    for (int kt = 0; kt <= qt; ++kt) {
        __syncthreads();
        {
            const size_t base = ((size_t)(b * TT + kt * 64)) * 512 + hk * 128;
            for (int idx = tid; idx < 1024; idx += 128) {
                int r = idx >> 4, c = (idx & 15) << 3;
                size_t g = base + (size_t)r * 512 + c;
                uint32_t so = (uint32_t)(r * AST + c) * 2;
                cp_async16(aKh + so, Kh + g);
                cp_async16(aKl + so, Kl + g);
                cp_async16(aVh + so, Vh + g);
                cp_async16(aVl + so, Vl + g);
            }
            CP_COMMIT();
            CP_WAIT0();
        }
        __syncthreads();

        // ---- S = Q K^T (bf16x3) ----
        float sacc[8][4];
        #pragma unroll
        for (int i = 0; i < 8; ++i)
            #pragma unroll
            for (int r = 0; r < 4; ++r) sacc[i][r] = 0.f;

        #pragma unroll
        for (int ks = 0; ks < 8; ++ks) {
            uint32_t ah[4], al[4];
            uint32_t qoff = ((wm * 16 + ldRow) * AST + ks * 16 + ldCol) * 2;
            ldm_x4(ah[0], ah[1], ah[2], ah[3], aQh + qoff);
            ldm_x4(al[0], al[1], al[2], al[3], aQl + qoff);
            #pragma unroll
            for (int j = 0; j < 4; ++j) {
                uint32_t koff = ((j * 16 + ldRow) * AST + ks * 16 + ldCol) * 2;
                uint32_t r0, r1, r2, r3;
                ldm_x4(r0, r1, r2, r3, aKh + koff);
                uint32_t bh0[2] = {r0, r2}, bh1[2] = {r1, r3};
                mma16816(sacc[2 * j], ah, bh0);
                mma16816(sacc[2 * j + 1], ah, bh1);
                mma16816(sacc[2 * j], al, bh0);
                mma16816(sacc[2 * j + 1], al, bh1);
                ldm_x4(r0, r1, r2, r3, aKl + koff);
                uint32_t bl0[2] = {r0, r2}, bl1[2] = {r1, r3};
                mma16816(sacc[2 * j], ah, bl0);
                mma16816(sacc[2 * j + 1], ah, bl1);
            }
        }

        // ---- causal mask (diagonal tile only) ----
        if (kt == qt) {
            int lr0 = wm * 16 + gid, lr1 = lr0 + 8;
            #pragma unroll
            for (int nb = 0; nb < 8; ++nb) {
                int lc = nb * 8 + tig * 2;
                if (lc > lr0)     sacc[nb][0] = -1e30f;
                if (lc + 1 > lr0) sacc[nb][1] = -1e30f;
                if (lc > lr1)     sacc[nb][2] = -1e30f;
                if (lc + 1 > lr1) sacc[nb][3] = -1e30f;
            }
        }

        // ---- online softmax ----
        #pragma unroll
        for (int hf = 0; hf < 2; ++hf) {
            float rmax = -1e30f;
            #pragma unroll
            for (int nb = 0; nb < 8; ++nb)
                rmax = fmaxf(rmax, fmaxf(sacc[nb][hf * 2], sacc[nb][hf * 2 + 1]));
            rmax = fmaxf(rmax, __shfl_xor_sync(0xffffffffu, rmax, 1));
            rmax = fmaxf(rmax, __shfl_xor_sync(0xffffffffu, rmax, 2));
            float mnew = fmaxf(mrow[hf], rmax);
            float f = __expf(mrow[hf] - mnew);
            mrow[hf] = mnew;
            float rsum = 0.f;
            #pragma unroll
            for (int nb = 0; nb < 8; ++nb) {
                float s0 = __expf(sacc[nb][hf * 2] - mnew);
                float s1 = __expf(sacc[nb][hf * 2 + 1] - mnew);
                sacc[nb][hf * 2] = s0;
                sacc[nb][hf * 2 + 1] = s1;
                rsum += s0 + s1;
            }
            rsum += __shfl_xor_sync(0xffffffffu, rsum, 1);
            rsum += __shfl_xor_sync(0xffffffffu, rsum, 2);
            lrow[hf] = lrow[hf] * f + rsum;
            #pragma unroll
            for (int nb = 0; nb < 16; ++nb) {
                oacc[nb][hf * 2] *= f;
                oacc[nb][hf * 2 + 1] *= f;
            }
        }

        // ---- P -> A-fragments (hi/lo) ----
        uint32_t ph[4][4], pl[4][4];
        #pragma unroll
        for (int ks = 0; ks < 4; ++ks) {
            split2(sacc[2 * ks][0], sacc[2 * ks][1], ph[ks][0], pl[ks][0]);
            split2(sacc[2 * ks][2], sacc[2 * ks][3], ph[ks][1], pl[ks][1]);
            split2(sacc[2 * ks + 1][0], sacc[2 * ks + 1][1], ph[ks][2], pl[ks][2]);
            split2(sacc[2 * ks + 1][2], sacc[2 * ks + 1][3], ph[ks][3], pl[ks][3]);
        }

        // ---- O += P V (bf16x3) ----
        #pragma unroll
        for (int ks = 0; ks < 4; ++ks) {
            #pragma unroll
            for (int j = 0; j < 8; ++j) {
                uint32_t voff = ((ks * 16 + ldRow) * AST + j * 16 + ldCol) * 2;
                uint32_t r0, r1, r2, r3;
                ldm_x4t(r0, r1, r2, r3, aVh + voff);
                uint32_t vh0[2] = {r0, r1}, vh1[2] = {r2, r3};
                mma16816(oacc[2 * j], ph[ks], vh0);
                mma16816(oacc[2 * j + 1], ph[ks], vh1);
                mma16816(oacc[2 * j], pl[ks], vh0);
                mma16816(oacc[2 * j + 1], pl[ks], vh1);
                ldm_x4t(r0, r1, r2, r3, aVl + voff);
                uint32_t vl0[2] = {r0, r1}, vl1[2] = {r2, r3};
                mma16816(oacc[2 * j], ph[ks], vl0);
                mma16816(oacc[2 * j + 1], ph[ks], vl1);
            }
        }
    }

    // ---- epilogue: write hi/lo bf16 directly into abf layout [m][2*2048] ----
    float inv0 = 1.f / lrow[0], inv1 = 1.f / lrow[1];
    size_t row0 = (size_t)(b * TT + qBase + wm * 16 + gid);
    __nv_bfloat16* p0 = Oo + row0 * (2 * KDIM) + h * 128 + tig * 2;
    __nv_bfloat16* p1 = Oo + (row0 + 8) * (2 * KDIM) + h * 128 + tig * 2;
    #pragma unroll
    for (int nb = 0; nb < 16; ++nb) {
        uint32_t hi, lo;
        split2(oacc[nb][0] * inv0, oacc[nb][1] * inv0, hi, lo);
        *(uint32_t*)(p0 + nb * 8) = hi;
        *(uint32_t*)(p0 + KDIM + nb * 8) = lo;
        split2(oacc[nb][2] * inv1, oacc[nb][3] * inv1, hi, lo);
        *(uint32_t*)(p1 + nb * 8) = hi;
        *(uint32_t*)(p1 + KDIM + nb * 8) = lo;
    }
}

// ---------------- launcher ---------------------------------------------------
extern "C" void kernel_launch(void* const* d_in, const int* in_sizes, int n_in,
                              void* d_out, int out_size)
{
    const float* x  = (const float*)d_in[0];
    const float* wq = (const float*)d_in[1];
    const float* wk = (const float*)d_in[2];
    const float* wv = (const float*)d_in[3];
    const float* wo = (const float*)d_in[4];
    float* out = (float*)d_out;

    float *Qb, *Kb, *Vb;
    __nv_bfloat16 *xbf, *abf, *wqt, *wkt, *wvt, *wot;
    __nv_bfloat16 *qh, *ql, *kh, *kl, *vh, *vl;
    cudaGetSymbolAddress((void**)&Qb, g_Q);
    cudaGetSymbolAddress((void**)&Kb, g_K);
    cudaGetSymbolAddress((void**)&Vb, g_V);
    cudaGetSymbolAddress((void**)&xbf, g_xbf);
    cudaGetSymbolAddress((void**)&abf, g_abf);
    cudaGetSymbolAddress((void**)&wqt, g_wqt);
    cudaGetSymbolAddress((void**)&wkt, g_wkt);
    cudaGetSymbolAddress((void**)&wvt, g_wvt);
    cudaGetSymbolAddress((void**)&wot, g_wot);
    cudaGetSymbolAddress((void**)&qh, g_Qh);
    cudaGetSymbolAddress((void**)&ql, g_Ql);
    cudaGetSymbolAddress((void**)&kh, g_Kh);
    cudaGetSymbolAddress((void**)&kl, g_Kl);
    cudaGetSymbolAddress((void**)&vh, g_Vh);
    cudaGetSymbolAddress((void**)&vl, g_Vl);

    cudaFuncSetAttribute(attn_mma_kernel,
                         cudaFuncAttributeMaxDynamicSharedMemorySize, ATT_SMEM);
    cudaFuncSetAttribute(gemm3_kernel,
                         cudaFuncAttributeMaxDynamicSharedMemorySize, G_SMEM_B);

    // launches 1-5: conversions (6th launch = Q-proj gemm3 for ncu -s 5 -c 1)
    tsplit_kernel<<<dim3(2048 / 32, KDIM / 32), 256>>>(wq, wqt, 2048);
    tsplit_kernel<<<dim3(512 / 32,  KDIM / 32), 256>>>(wk, wkt, 512);
    tsplit_kernel<<<dim3(512 / 32,  KDIM / 32), 256>>>(wv, wvt, 512);
    tsplit_kernel<<<dim3(2048 / 32, KDIM / 32), 256>>>(wo, wot, 2048);
    split_kernel<<<(BT * KDIM + 255) / 256, 256>>>(x, xbf);

    // QKV projections (bf16x3 tensor-core GEMM, cp.async pipelined)
    gemm3_kernel<<<dim3(2048 / 128, BT / 128), 256, G_SMEM_B>>>(xbf, wqt, Qb, 2048, KDIM);
    gemm3_kernel<<<dim3(512 / 128,  BT / 128), 256, G_SMEM_B>>>(xbf, wkt, Kb, 512, KDIM);
    gemm3_kernel<<<dim3(512 / 128,  BT / 128), 256, G_SMEM_B>>>(xbf, wvt, Vb, 512, KDIM);

    // RoPE table + RoPE/hi-lo splits
    rope_table_kernel<<<(TT * 64 + 255) / 256, 256>>>();
    rope_split_kernel<<<(BT * 1024 + 255) / 256, 256>>>(Qb, qh, ql, 2048,
                                                        0.08838834764831845f);
    rope_split_kernel<<<(BT * 256 + 255) / 256, 256>>>(Kb, kh, kl, 512, 1.0f);
    split_plain_kernel<<<(BT * 512 + 255) / 256, 256>>>(Vb, vh, vl, BT * 512);

    // tensor-core flash attention -> abf (hi/lo)
    attn_mma_kernel<<<dim3(TT / 64, NH, BB), 128, ATT_SMEM>>>(qh, ql, kh, kl,
                                                              vh, vl, abf);

    // Output projection
    gemm3_kernel<<<dim3(2048 / 128, BT / 128), 256, G_SMEM_B>>>(abf, wot, out, 2048, KDIM);
}

// round 10
// speedup vs baseline: 7.7380x; 2.4772x over previous
#include <cuda_runtime.h>
#include <cuda_fp16.h>
#include <math.h>
#include <stdint.h>

#define BB   2
#define TT   2048
#define DD   2048
#define NH   16
#define NKV  4
#define HDQ  128
#define BT   4096   // BB*TT
#define KDIM 2048

// ---------------- scratch (static device globals: no allocs allowed) --------
__device__ float g_Q[(size_t)BT * (NH * HDQ)];
__device__ float g_K[(size_t)BT * (NKV * HDQ)];
__device__ float g_V[(size_t)BT * (NKV * HDQ)];

__device__ __half g_xh[(size_t)BT * KDIM];        // x fp16 [M][K]
__device__ __half g_ah[(size_t)BT * KDIM];        // attn-out fp16 [M][K]
__device__ __half g_wqt[(size_t)2048 * KDIM];     // [N][K]
__device__ __half g_wkt[(size_t)512  * KDIM];
__device__ __half g_wvt[(size_t)512  * KDIM];
__device__ __half g_wot[(size_t)2048 * KDIM];
__device__ float g_rcos[TT * 64];
__device__ float g_rsin[TT * 64];

// attention operands fp16
__device__ __half g_Qf[(size_t)BT * 2048];
__device__ __half g_Kf[(size_t)BT * 512];
__device__ __half g_Vf[(size_t)BT * 512];

// ---------------- helpers ----------------------------------------------------
__device__ __forceinline__ uint32_t smem_u32(const void* p) {
    uint32_t a;
    asm("{ .reg .u64 t; cvta.to.shared.u64 t, %1; cvt.u32.u64 %0, t; }"
        : "=r"(a) : "l"(p));
    return a;
}
__device__ __forceinline__ void ldm_x4(uint32_t& r0, uint32_t& r1,
                                       uint32_t& r2, uint32_t& r3, uint32_t addr) {
    asm volatile("ldmatrix.sync.aligned.m8n8.x4.shared.b16 {%0,%1,%2,%3}, [%4];"
                 : "=r"(r0), "=r"(r1), "=r"(r2), "=r"(r3) : "r"(addr));
}
__device__ __forceinline__ void ldm_x4t(uint32_t& r0, uint32_t& r1,
                                        uint32_t& r2, uint32_t& r3, uint32_t addr) {
    asm volatile("ldmatrix.sync.aligned.m8n8.x4.trans.shared.b16 {%0,%1,%2,%3}, [%4];"
                 : "=r"(r0), "=r"(r1), "=r"(r2), "=r"(r3) : "r"(addr));
}
__device__ __forceinline__ void mma16816(float* d, const uint32_t* a, const uint32_t* b) {
    asm volatile("mma.sync.aligned.m16n8k16.row.col.f32.f16.f16.f32 "
                 "{%0,%1,%2,%3}, {%4,%5,%6,%7}, {%8,%9}, {%0,%1,%2,%3};"
                 : "+f"(d[0]), "+f"(d[1]), "+f"(d[2]), "+f"(d[3])
                 : "r"(a[0]), "r"(a[1]), "r"(a[2]), "r"(a[3]),
                   "r"(b[0]), "r"(b[1]));
}
__device__ __forceinline__ void cp_async16(uint32_t saddr, const void* gaddr) {
    asm volatile("cp.async.cg.shared.global [%0], [%1], 16;"
                 :: "r"(saddr), "l"(gaddr) : "memory");
}
#define CP_COMMIT() asm volatile("cp.async.commit_group;" ::: "memory")
#define CP_WAIT1()  asm volatile("cp.async.wait_group 1;" ::: "memory")
#define CP_WAIT0()  asm volatile("cp.async.wait_group 0;" ::: "memory")

__device__ __forceinline__ uint32_t pack_h2(float a, float b) {
    __half2 t = __floats2half2_rn(a, b);
    return *reinterpret_cast<uint32_t*>(&t);
}

// ---------------- conversion kernels ----------------------------------------
__global__ void conv_kernel(const float* __restrict__ A, __half* __restrict__ O, int n)
{
    int idx = blockIdx.x * blockDim.x + threadIdx.x;
    if (idx >= n) return;
    O[idx] = __float2half(A[idx]);
}
// transpose+convert: W[K=2048][N] fp32 -> Wt[N][K] fp16
__global__ void tconv_kernel(const float* __restrict__ W, __half* __restrict__ Wt, int N)
{
    __shared__ float tile[32][33];
    int tx = threadIdx.x & 31, ty = threadIdx.x >> 5;
    int nb = blockIdx.x * 32, kb = blockIdx.y * 32;
    #pragma unroll
    for (int r = 0; r < 4; ++r)
        tile[ty + r * 8][tx] = W[(size_t)(kb + ty + r * 8) * N + nb + tx];
    __syncthreads();
    #pragma unroll
    for (int r = 0; r < 4; ++r) {
        int n = nb + ty + r * 8;
        Wt[(size_t)n * KDIM + kb + tx] = __float2half(tile[tx][ty + r * 8]);
    }
}

// ---------------- fp16 GEMM via mma.sync + cp.async 3-stage pipeline ---------
// C[M,N] = A[M,K] @ Bt[N,K]^T.  128x128x32 tile, 256 threads, 8 warps (4m x 2n).
#define GSTAGE_H   (128 * 40)
#define G_SMEM_B   (6 * GSTAGE_H * 2)      // 61440 bytes

__global__ __launch_bounds__(256, 2) void gemm_kernel(
    const __half* __restrict__ A, const __half* __restrict__ Bt,
    float* __restrict__ C, int N, int K)
{
    extern __shared__ __half gsm[];
    const uint32_t smb = smem_u32(gsm);

    const int tid = threadIdx.x;
    const int lane = tid & 31, wid = tid >> 5;
    const int wm = wid & 3, wn = wid >> 2;
    const int mBase = blockIdx.y << 7, nBase = blockIdx.x << 7;
    const int NC = K >> 5;

    const int lrow = tid >> 1;
    const int lseg = (tid & 1) << 4;
    const int ldRow = lane & 15;
    const int ldCol = (lane >> 4) << 3;

    const __half* gA = A  + (size_t)(mBase + lrow) * K + lseg;
    const __half* gB = Bt + (size_t)(nBase + lrow) * K + lseg;
    const uint32_t sOff = (uint32_t)(lrow * 40 + lseg) * 2;

    float acc[2][8][4];
    #pragma unroll
    for (int i = 0; i < 2; ++i)
        #pragma unroll
        for (int j = 0; j < 8; ++j)
            #pragma unroll
            for (int r = 0; r < 4; ++r) acc[i][j][r] = 0.f;

    auto issue = [&](int c, int s) {
        const __half* ga = gA + c * 32;
        const __half* gb = gB + c * 32;
        uint32_t sa = smb + (uint32_t)s * (GSTAGE_H * 2) + sOff;
        uint32_t sb = smb + (uint32_t)(3 * GSTAGE_H * 2) + (uint32_t)s * (GSTAGE_H * 2) + sOff;
        cp_async16(sa,      ga);
        cp_async16(sa + 16, ga + 8);
        cp_async16(sb,      gb);
        cp_async16(sb + 16, gb + 8);
        CP_COMMIT();
    };

    issue(0, 0);
    issue(1, 1);

    int stage = 0;
    for (int c = 0; c < NC; ++c) {
        if (c + 1 < NC) CP_WAIT1(); else CP_WAIT0();
        __syncthreads();
        if (c + 2 < NC) {
            int ns = stage + 2; if (ns >= 3) ns -= 3;
            issue(c + 2, ns);
        }

        const uint32_t sA = smb + (uint32_t)stage * (GSTAGE_H * 2);
        const uint32_t sB = smb + (uint32_t)(3 * GSTAGE_H * 2) + (uint32_t)stage * (GSTAGE_H * 2);
        #pragma unroll
        for (int ks = 0; ks < 2; ++ks) {
            uint32_t af[2][4], bfr[8][2];
            #pragma unroll
            for (int mf = 0; mf < 2; ++mf) {
                uint32_t addr = sA + ((wm * 32 + mf * 16 + ldRow) * 40
                                      + ks * 16 + ldCol) * 2;
                ldm_x4(af[mf][0], af[mf][1], af[mf][2], af[mf][3], addr);
            }
            #pragma unroll
            for (int ng = 0; ng < 4; ++ng) {
                uint32_t r0, r1, r2, r3;
                uint32_t addr = sB + ((wn * 64 + ng * 16 + ldRow) * 40
                                      + ks * 16 + ldCol) * 2;
                ldm_x4(r0, r1, r2, r3, addr);
                bfr[ng * 2 + 0][0] = r0; bfr[ng * 2 + 1][0] = r1;
                bfr[ng * 2 + 0][1] = r2; bfr[ng * 2 + 1][1] = r3;
            }
            #pragma unroll
            for (int mf = 0; mf < 2; ++mf)
                #pragma unroll
                for (int nf = 0; nf < 8; ++nf)
                    mma16816(acc[mf][nf], af[mf], bfr[nf]);
        }
        ++stage; if (stage == 3) stage = 0;
        __syncthreads();
    }

    const int gid = lane >> 2, tig = lane & 3;
    #pragma unroll
    for (int mf = 0; mf < 2; ++mf) {
        #pragma unroll
        for (int nf = 0; nf < 8; ++nf) {
            int row = mBase + wm * 32 + mf * 16 + gid;
            int col = nBase + wn * 64 + nf * 8 + tig * 2;
            float2 v0 = make_float2(acc[mf][nf][0], acc[mf][nf][1]);
            float2 v1 = make_float2(acc[mf][nf][2], acc[mf][nf][3]);
            *(float2*)&C[(size_t)row * N + col] = v0;
            *(float2*)&C[(size_t)(row + 8) * N + col] = v1;
        }
    }
}

// ---------------- RoPE table, rope+convert -----------------------------------
__global__ void rope_table_kernel()
{
    int idx = blockIdx.x * blockDim.x + threadIdx.x;
    if (idx >= TT * 64) return;
    int t = idx >> 6, d = idx & 63;
    double inv = exp2(-(double)d * (19.931568569324174 / 64.0));
    double ang = (double)t * inv;
    g_rcos[idx] = (float)cos(ang);
    g_rsin[idx] = (float)sin(ang);
}
__global__ void rope_conv_kernel(const float* __restrict__ in,
                                 __half* __restrict__ H, int cols, float scale)
{
    int idx = blockIdx.x * blockDim.x + threadIdx.x;
    int ppr = cols >> 1;
    if (idx >= BT * ppr) return;
    int row = idx / ppr;
    int p = idx - row * ppr;
    int h = p >> 6, d = p & 63;
    int t = row & (TT - 1);
    size_t base = (size_t)row * cols + h * 128 + d;
    float u1 = in[base];
    float u2 = in[base + 64];
    float c = g_rcos[t * 64 + d];
    float s = g_rsin[t * 64 + d];
    H[base]      = __float2half((u1 * c - u2 * s) * scale);
    H[base + 64] = __float2half((u2 * c + u1 * s) * scale);
}

// ---------------- fp16 tensor-core flash attention ---------------------------
// CTA: 64 q rows, 4 warps, BN=64 kv per tile, D=128. Single fp16 pass.
#define AST 136
#define ATT_SMEM (3 * 64 * AST * 2)

__global__ __launch_bounds__(128) void attn_mma_kernel(
    const __half* __restrict__ Qf, const __half* __restrict__ Kf,
    const __half* __restrict__ Vf, __half* __restrict__ Oo)
{
    extern __shared__ __half smh[];
    __half* sQ = smh;
    __half* sK = sQ + 64 * AST;
    __half* sV = sK + 64 * AST;

    const int tid = threadIdx.x;
    const int lane = tid & 31, wm = tid >> 5;
    const int gid = lane >> 2, tig = lane & 3;
    const int ldRow = lane & 15, ldCol = (lane >> 4) << 3;
    const int qt = gridDim.x - 1 - blockIdx.x;
    const int h = blockIdx.y, b = blockIdx.z;
    const int hk = h >> 2;
    const int qBase = qt * 64;

    {
        const __half* gq = Qf + ((size_t)(b * TT + qBase)) * 2048 + h * 128;
        for (int idx = tid; idx < 1024; idx += 128) {
            int r = idx >> 4, c = (idx & 15) << 3;
            *(uint4*)&sQ[r * AST + c] = *(const uint4*)(gq + (size_t)r * 2048 + c);
        }
    }

    float oacc[16][4];
    #pragma unroll
    for (int i = 0; i < 16; ++i)
        #pragma unroll
        for (int r = 0; r < 4; ++r) oacc[i][r] = 0.f;
    float mrow[2] = {-INFINITY, -INFINITY};
    float lrow[2] = {0.f, 0.f};

    const uint32_t aQ = smem_u32(sQ);
    const uint32_t aK = smem_u32(sK);
    const uint32_t aV = smem_u32(sV);

    for (int kt = 0; kt <= qt; ++kt) {
        __syncthreads();
        {
            const size_t base = ((size_t)(b * TT + kt * 64)) * 512 + hk * 128;
            for (int idx = tid; idx < 1024; idx += 128) {
                int r = idx >> 4, c = (idx & 15) << 3;
                size_t g = base + (size_t)r * 512 + c;
                uint32_t so = (uint32_t)(r * AST + c) * 2;
                cp_async16(aK + so, Kf + g);
                cp_async16(aV + so, Vf + g);
            }
            CP_COMMIT();
            CP_WAIT0();
        }
        __syncthreads();

        // ---- S = Q K^T ----
        float sacc[8][4];
        #pragma unroll
        for (int i = 0; i < 8; ++i)
            #pragma unroll
            for (int r = 0; r < 4; ++r) sacc[i][r] = 0.f;

        #pragma unroll
        for (int ks = 0; ks < 8; ++ks) {
            uint32_t aq[4];
            uint32_t qoff = ((wm * 16 + ldRow) * AST + ks * 16 + ldCol) * 2;
            ldm_x4(aq[0], aq[1], aq[2], aq[3], aQ + qoff);
            #pragma unroll
            for (int j = 0; j < 4; ++j) {
                uint32_t koff = ((j * 16 + ldRow) * AST + ks * 16 + ldCol) * 2;
                uint32_t r0, r1, r2, r3;
                ldm_x4(r0, r1, r2, r3, aK + koff);
                uint32_t b0[2] = {r0, r2}, b1[2] = {r1, r3};
                mma16816(sacc[2 * j], aq, b0);
                mma16816(sacc[2 * j + 1], aq, b1);
            }
        }

        // ---- causal mask (diagonal tile only) ----
        if (kt == qt) {
            int lr0 = wm * 16 + gid, lr1 = lr0 + 8;
            #pragma unroll
            for (int nb = 0; nb < 8; ++nb) {
                int lc = nb * 8 + tig * 2;
                if (lc > lr0)     sacc[nb][0] = -1e30f;
                if (lc + 1 > lr0) sacc[nb][1] = -1e30f;
                if (lc > lr1)     sacc[nb][2] = -1e30f;
                if (lc + 1 > lr1) sacc[nb][3] = -1e30f;
            }
        }

        // ---- online softmax ----
        #pragma unroll
        for (int hf = 0; hf < 2; ++hf) {
            float rmax = -1e30f;
            #pragma unroll
            for (int nb = 0; nb < 8; ++nb)
                rmax = fmaxf(rmax, fmaxf(sacc[nb][hf * 2], sacc[nb][hf * 2 + 1]));
            rmax = fmaxf(rmax, __shfl_xor_sync(0xffffffffu, rmax, 1));
            rmax = fmaxf(rmax, __shfl_xor_sync(0xffffffffu, rmax, 2));
            float mnew = fmaxf(mrow[hf], rmax);
            float f = __expf(mrow[hf] - mnew);
            mrow[hf] = mnew;
            float rsum = 0.f;
            #pragma unroll
            for (int nb = 0; nb < 8; ++nb) {
                float s0 = __expf(sacc[nb][hf * 2] - mnew);
                float s1 = __expf(sacc[nb][hf * 2 + 1] - mnew);
                sacc[nb][hf * 2] = s0;
                sacc[nb][hf * 2 + 1] = s1;
                rsum += s0 + s1;
            }
            rsum += __shfl_xor_sync(0xffffffffu, rsum, 1);
            rsum += __shfl_xor_sync(0xffffffffu, rsum, 2);
            lrow[hf] = lrow[hf] * f + rsum;
            #pragma unroll
            for (int nb = 0; nb < 16; ++nb) {
                oacc[nb][hf * 2] *= f;
                oacc[nb][hf * 2 + 1] *= f;
            }
        }

        // ---- P -> fp16 A-fragments ----
        uint32_t ph[4][4];
        #pragma unroll
        for (int ks = 0; ks < 4; ++ks) {
            ph[ks][0] = pack_h2(sacc[2 * ks][0], sacc[2 * ks][1]);
            ph[ks][1] = pack_h2(sacc[2 * ks][2], sacc[2 * ks][3]);
            ph[ks][2] = pack_h2(sacc[2 * ks + 1][0], sacc[2 * ks + 1][1]);
            ph[ks][3] = pack_h2(sacc[2 * ks + 1][2], sacc[2 * ks + 1][3]);
        }

        // ---- O += P V ----
        #pragma unroll
        for (int ks = 0; ks < 4; ++ks) {
            #pragma unroll
            for (int j = 0; j < 8; ++j) {
                uint32_t voff = ((ks * 16 + ldRow) * AST + j * 16 + ldCol) * 2;
                uint32_t r0, r1, r2, r3;
                ldm_x4t(r0, r1, r2, r3, aV + voff);
                uint32_t v0[2] = {r0, r1}, v1[2] = {r2, r3};
                mma16816(oacc[2 * j], ph[ks], v0);
                mma16816(oacc[2 * j + 1], ph[ks], v1);
            }
        }
    }

    // ---- epilogue: write fp16 directly into ah layout [m][2048] ----
    float inv0 = 1.f / lrow[0], inv1 = 1.f / lrow[1];
    size_t row0 = (size_t)(b * TT + qBase + wm * 16 + gid);
    __half* p0 = Oo + row0 * KDIM + h * 128 + tig * 2;
    __half* p1 = Oo + (row0 + 8) * KDIM + h * 128 + tig * 2;
    #pragma unroll
    for (int nb = 0; nb < 16; ++nb) {
        *(uint32_t*)(p0 + nb * 8) = pack_h2(oacc[nb][0] * inv0, oacc[nb][1] * inv0);
        *(uint32_t*)(p1 + nb * 8) = pack_h2(oacc[nb][2] * inv1, oacc[nb][3] * inv1);
    }
}

// ---------------- launcher ---------------------------------------------------
extern "C" void kernel_launch(void* const* d_in, const int* in_sizes, int n_in,
                              void* d_out, int out_size)
{
    const float* x  = (const float*)d_in[0];
    const float* wq = (const float*)d_in[1];
    const float* wk = (const float*)d_in[2];
    const float* wv = (const float*)d_in[3];
    const float* wo = (const float*)d_in[4];
    float* out = (float*)d_out;

    float *Qb, *Kb, *Vb;
    __half *xh, *ah, *wqt, *wkt, *wvt, *wot, *qf, *kf, *vf;
    cudaGetSymbolAddress((void**)&Qb, g_Q);
    cudaGetSymbolAddress((void**)&Kb, g_K);
    cudaGetSymbolAddress((void**)&Vb, g_V);
    cudaGetSymbolAddress((void**)&xh, g_xh);
    cudaGetSymbolAddress((void**)&ah, g_ah);
    cudaGetSymbolAddress((void**)&wqt, g_wqt);
    cudaGetSymbolAddress((void**)&wkt, g_wkt);
    cudaGetSymbolAddress((void**)&wvt, g_wvt);
    cudaGetSymbolAddress((void**)&wot, g_wot);
    cudaGetSymbolAddress((void**)&qf, g_Qf);
    cudaGetSymbolAddress((void**)&kf, g_Kf);
    cudaGetSymbolAddress((void**)&vf, g_Vf);

    cudaFuncSetAttribute(attn_mma_kernel,
                         cudaFuncAttributeMaxDynamicSharedMemorySize, ATT_SMEM);
    cudaFuncSetAttribute(gemm_kernel,
                         cudaFuncAttributeMaxDynamicSharedMemorySize, G_SMEM_B);

    // conversions (launches 1-5)
    tconv_kernel<<<dim3(2048 / 32, KDIM / 32), 256>>>(wq, wqt, 2048);
    tconv_kernel<<<dim3(512 / 32,  KDIM / 32), 256>>>(wk, wkt, 512);
    tconv_kernel<<<dim3(512 / 32,  KDIM / 32), 256>>>(wv, wvt, 512);
    tconv_kernel<<<dim3(2048 / 32, KDIM / 32), 256>>>(wo, wot, 2048);
    conv_kernel<<<(BT * KDIM + 255) / 256, 256>>>(x, xh, BT * KDIM);

    // QKV projections (fp16 tensor-core GEMM)
    gemm_kernel<<<dim3(2048 / 128, BT / 128), 256, G_SMEM_B>>>(xh, wqt, Qb, 2048, KDIM);
    gemm_kernel<<<dim3(512 / 128,  BT / 128), 256, G_SMEM_B>>>(xh, wkt, Kb, 512, KDIM);
    gemm_kernel<<<dim3(512 / 128,  BT / 128), 256, G_SMEM_B>>>(xh, wvt, Vb, 512, KDIM);

    // RoPE table + RoPE/convert (Q pre-scaled by 1/sqrt(128)); V convert
    rope_table_kernel<<<(TT * 64 + 255) / 256, 256>>>();
    rope_conv_kernel<<<(BT * 1024 + 255) / 256, 256>>>(Qb, qf, 2048,
                                                       0.08838834764831845f);
    rope_conv_kernel<<<(BT * 256 + 255) / 256, 256>>>(Kb, kf, 512, 1.0f);
    conv_kernel<<<(BT * 512 + 255) / 256, 256>>>(Vb, vf, BT * 512);

    // fp16 tensor-core flash attention -> ah
    attn_mma_kernel<<<dim3(TT / 64, NH, BB), 128, ATT_SMEM>>>(qf, kf, vf, ah);

    // Output projection
    gemm_kernel<<<dim3(2048 / 128, BT / 128), 256, G_SMEM_B>>>(ah, wot, out, 2048, KDIM);
}

// round 12
// speedup vs baseline: 8.2366x; 1.0644x over previous
#include <cuda_runtime.h>
#include <cuda_fp16.h>
#include <math.h>
#include <stdint.h>

#define BB   2
#define TT   2048
#define DD   2048
#define NH   16
#define NKV  4
#define HDQ  128
#define BT   4096   // BB*TT
#define KDIM 2048
#define NQKV 3072   // fused Q(2048)+K(512)+V(512) output width

// ---------------- scratch (static device globals: no allocs allowed) --------
__device__ float g_QKV[(size_t)BT * NQKV];        // fused projection output (fp32)

__device__ __half g_xh[(size_t)BT * KDIM];        // x fp16 [M][K]
__device__ __half g_ah[(size_t)BT * KDIM];        // attn-out fp16 [M][K]
__device__ __half g_wqkvt[(size_t)NQKV * KDIM];   // fused [N][K] fp16 weights
__device__ __half g_wot[(size_t)2048 * KDIM];
__device__ float g_rcos[TT * 64];
__device__ float g_rsin[TT * 64];

// attention operands fp16
__device__ __half g_Qf[(size_t)BT * 2048];
__device__ __half g_Kf[(size_t)BT * 512];
__device__ __half g_Vf[(size_t)BT * 512];

// ---------------- helpers ----------------------------------------------------
__device__ __forceinline__ uint32_t smem_u32(const void* p) {
    uint32_t a;
    asm("{ .reg .u64 t; cvta.to.shared.u64 t, %1; cvt.u32.u64 %0, t; }"
        : "=r"(a) : "l"(p));
    return a;
}
__device__ __forceinline__ void ldm_x4(uint32_t& r0, uint32_t& r1,
                                       uint32_t& r2, uint32_t& r3, uint32_t addr) {
    asm volatile("ldmatrix.sync.aligned.m8n8.x4.shared.b16 {%0,%1,%2,%3}, [%4];"
                 : "=r"(r0), "=r"(r1), "=r"(r2), "=r"(r3) : "r"(addr));
}
__device__ __forceinline__ void ldm_x4t(uint32_t& r0, uint32_t& r1,
                                        uint32_t& r2, uint32_t& r3, uint32_t addr) {
    asm volatile("ldmatrix.sync.aligned.m8n8.x4.trans.shared.b16 {%0,%1,%2,%3}, [%4];"
                 : "=r"(r0), "=r"(r1), "=r"(r2), "=r"(r3) : "r"(addr));
}
__device__ __forceinline__ void mma16816(float* d, const uint32_t* a, const uint32_t* b) {
    asm volatile("mma.sync.aligned.m16n8k16.row.col.f32.f16.f16.f32 "
                 "{%0,%1,%2,%3}, {%4,%5,%6,%7}, {%8,%9}, {%0,%1,%2,%3};"
                 : "+f"(d[0]), "+f"(d[1]), "+f"(d[2]), "+f"(d[3])
                 : "r"(a[0]), "r"(a[1]), "r"(a[2]), "r"(a[3]),
                   "r"(b[0]), "r"(b[1]));
}
__device__ __forceinline__ void cp_async16(uint32_t saddr, const void* gaddr) {
    asm volatile("cp.async.cg.shared.global [%0], [%1], 16;"
                 :: "r"(saddr), "l"(gaddr) : "memory");
}
#define CP_COMMIT() asm volatile("cp.async.commit_group;" ::: "memory")
#define CP_WAIT1()  asm volatile("cp.async.wait_group 1;" ::: "memory")
#define CP_WAIT0()  asm volatile("cp.async.wait_group 0;" ::: "memory")

__device__ __forceinline__ uint32_t pack_h2(float a, float b) {
    __half2 t = __floats2half2_rn(a, b);
    return *reinterpret_cast<uint32_t*>(&t);
}

// ---------------- conversion kernels ----------------------------------------
// vectorized fp32 -> fp16 (n divisible by 4)
__global__ void conv4_kernel(const float* __restrict__ A, __half* __restrict__ O, int n4)
{
    int idx = blockIdx.x * blockDim.x + threadIdx.x;
    if (idx >= n4) return;
    float4 v = ((const float4*)A)[idx];
    __half2 a = __floats2half2_rn(v.x, v.y);
    __half2 b = __floats2half2_rn(v.z, v.w);
    uint2 o = make_uint2(*reinterpret_cast<uint32_t*>(&a),
                         *reinterpret_cast<uint32_t*>(&b));
    ((uint2*)O)[idx] = o;
}
// strided segment conv: in rows stride instride, cols (div by 4), out compact
__global__ void conv4s_kernel(const float* __restrict__ A, __half* __restrict__ O,
                              int cols4, int instride)
{
    int idx = blockIdx.x * blockDim.x + threadIdx.x;
    if (idx >= BT * cols4) return;
    int m = idx / cols4, c4 = idx - m * cols4;
    float4 v = *(const float4*)(A + (size_t)m * instride + c4 * 4);
    __half2 a = __floats2half2_rn(v.x, v.y);
    __half2 b = __floats2half2_rn(v.z, v.w);
    uint2 o = make_uint2(*reinterpret_cast<uint32_t*>(&a),
                         *reinterpret_cast<uint32_t*>(&b));
    *(uint2*)(O + (size_t)m * (cols4 * 4) + c4 * 4) = o;
}
// transpose+convert: W[K=2048][N] fp32 -> Wt[N][K] fp16
__global__ void tconv_kernel(const float* __restrict__ W, __half* __restrict__ Wt, int N)
{
    __shared__ float tile[32][33];
    int tx = threadIdx.x & 31, ty = threadIdx.x >> 5;
    int nb = blockIdx.x * 32, kb = blockIdx.y * 32;
    #pragma unroll
    for (int r = 0; r < 4; ++r)
        tile[ty + r * 8][tx] = W[(size_t)(kb + ty + r * 8) * N + nb + tx];
    __syncthreads();
    #pragma unroll
    for (int r = 0; r < 4; ++r) {
        int n = nb + ty + r * 8;
        Wt[(size_t)n * KDIM + kb + tx] = __float2half(tile[tx][ty + r * 8]);
    }
}

// ---------------- fp16 GEMM via mma.sync + cp.async 3-stage pipeline ---------
#define GSTAGE_H   (128 * 40)
#define G_SMEM_B   (6 * GSTAGE_H * 2)      // 61440 bytes

__global__ __launch_bounds__(256, 2) void gemm_kernel(
    const __half* __restrict__ A, const __half* __restrict__ Bt,
    float* __restrict__ C, int N, int K)
{
    extern __shared__ __half gsm[];
    const uint32_t smb = smem_u32(gsm);

    const int tid = threadIdx.x;
    const int lane = tid & 31, wid = tid >> 5;
    const int wm = wid & 3, wn = wid >> 2;
    const int mBase = blockIdx.y << 7, nBase = blockIdx.x << 7;
    const int NC = K >> 5;

    const int lrow = tid >> 1;
    const int lseg = (tid & 1) << 4;
    const int ldRow = lane & 15;
    const int ldCol = (lane >> 4) << 3;

    const __half* gA = A  + (size_t)(mBase + lrow) * K + lseg;
    const __half* gB = Bt + (size_t)(nBase + lrow) * K + lseg;
    const uint32_t sOff = (uint32_t)(lrow * 40 + lseg) * 2;

    float acc[2][8][4];
    #pragma unroll
    for (int i = 0; i < 2; ++i)
        #pragma unroll
        for (int j = 0; j < 8; ++j)
            #pragma unroll
            for (int r = 0; r < 4; ++r) acc[i][j][r] = 0.f;

    auto issue = [&](int c, int s) {
        const __half* ga = gA + c * 32;
        const __half* gb = gB + c * 32;
        uint32_t sa = smb + (uint32_t)s * (GSTAGE_H * 2) + sOff;
        uint32_t sb = smb + (uint32_t)(3 * GSTAGE_H * 2) + (uint32_t)s * (GSTAGE_H * 2) + sOff;
        cp_async16(sa,      ga);
        cp_async16(sa + 16, ga + 8);
        cp_async16(sb,      gb);
        cp_async16(sb + 16, gb + 8);
        CP_COMMIT();
    };

    issue(0, 0);
    issue(1, 1);

    int stage = 0;
    for (int c = 0; c < NC; ++c) {
        if (c + 1 < NC) CP_WAIT1(); else CP_WAIT0();
        __syncthreads();
        if (c + 2 < NC) {
            int ns = stage + 2; if (ns >= 3) ns -= 3;
            issue(c + 2, ns);
        }

        const uint32_t sA = smb + (uint32_t)stage * (GSTAGE_H * 2);
        const uint32_t sB = smb + (uint32_t)(3 * GSTAGE_H * 2) + (uint32_t)stage * (GSTAGE_H * 2);
        #pragma unroll
        for (int ks = 0; ks < 2; ++ks) {
            uint32_t af[2][4], bfr[8][2];
            #pragma unroll
            for (int mf = 0; mf < 2; ++mf) {
                uint32_t addr = sA + ((wm * 32 + mf * 16 + ldRow) * 40
                                      + ks * 16 + ldCol) * 2;
                ldm_x4(af[mf][0], af[mf][1], af[mf][2], af[mf][3], addr);
            }
            #pragma unroll
            for (int ng = 0; ng < 4; ++ng) {
                uint32_t r0, r1, r2, r3;
                uint32_t addr = sB + ((wn * 64 + ng * 16 + ldRow) * 40
                                      + ks * 16 + ldCol) * 2;
                ldm_x4(r0, r1, r2, r3, addr);
                bfr[ng * 2 + 0][0] = r0; bfr[ng * 2 + 1][0] = r1;
                bfr[ng * 2 + 0][1] = r2; bfr[ng * 2 + 1][1] = r3;
            }
            #pragma unroll
            for (int mf = 0; mf < 2; ++mf)
                #pragma unroll
                for (int nf = 0; nf < 8; ++nf)
                    mma16816(acc[mf][nf], af[mf], bfr[nf]);
        }
        ++stage; if (stage == 3) stage = 0;
        // no trailing __syncthreads: the leading barrier of the next iteration
        // already orders "all warps finished stage s" before s is refilled.
    }

    const int gid = lane >> 2, tig = lane & 3;
    #pragma unroll
    for (int mf = 0; mf < 2; ++mf) {
        #pragma unroll
        for (int nf = 0; nf < 8; ++nf) {
            int row = mBase + wm * 32 + mf * 16 + gid;
            int col = nBase + wn * 64 + nf * 8 + tig * 2;
            float2 v0 = make_float2(acc[mf][nf][0], acc[mf][nf][1]);
            float2 v1 = make_float2(acc[mf][nf][2], acc[mf][nf][3]);
            *(float2*)&C[(size_t)row * N + col] = v0;
            *(float2*)&C[(size_t)(row + 8) * N + col] = v1;
        }
    }
}

// ---------------- RoPE table, rope+convert -----------------------------------
__global__ void rope_table_kernel()
{
    int idx = blockIdx.x * blockDim.x + threadIdx.x;
    if (idx >= TT * 64) return;
    int t = idx >> 6, d = idx & 63;
    double inv = exp2(-(double)d * (19.931568569324174 / 64.0));
    double ang = (double)t * inv;
    g_rcos[idx] = (float)cos(ang);
    g_rsin[idx] = (float)sin(ang);
}
// rope on a strided fp32 segment -> compact fp16. cols = n_heads*128
__global__ void rope_conv_kernel(const float* __restrict__ in,
                                 __half* __restrict__ H,
                                 int cols, int instride, float scale)
{
    int idx = blockIdx.x * blockDim.x + threadIdx.x;
    int ppr = cols >> 1;
    if (idx >= BT * ppr) return;
    int row = idx / ppr;
    int p = idx - row * ppr;
    int h = p >> 6, d = p & 63;
    int t = row & (TT - 1);
    const float* ip = in + (size_t)row * instride + h * 128 + d;
    float u1 = ip[0];
    float u2 = ip[64];
    float c = g_rcos[t * 64 + d];
    float s = g_rsin[t * 64 + d];
    __half* op = H + (size_t)row * cols + h * 128 + d;
    op[0]  = __float2half((u1 * c - u2 * s) * scale);
    op[64] = __float2half((u2 * c + u1 * s) * scale);
}

// ---------------- fp16 tensor-core flash attention (2-stage K/V pipeline) ----
#define AST 136
#define ATT_SMEM (5 * 64 * AST * 2)   // Q + 2 x (K,V) stages = 87040 B

__global__ __launch_bounds__(128) void attn_mma_kernel(
    const __half* __restrict__ Qf, const __half* __restrict__ Kf,
    const __half* __restrict__ Vf, __half* __restrict__ Oo)
{
    extern __shared__ __half smh[];
    __half* sQ = smh;                       // [64][AST]
    // stages: [K0][V0][K1][V1]
    __half* sKV = sQ + 64 * AST;

    const int tid = threadIdx.x;
    const int lane = tid & 31, wm = tid >> 5;
    const int gid = lane >> 2, tig = lane & 3;
    const int ldRow = lane & 15, ldCol = (lane >> 4) << 3;
    const int qt = gridDim.x - 1 - blockIdx.x;
    const int h = blockIdx.y, b = blockIdx.z;
    const int hk = h >> 2;
    const int qBase = qt * 64;

    const uint32_t aQ = smem_u32(sQ);
    const uint32_t aKV = smem_u32(sKV);
    const uint32_t stageB = 2 * 64 * AST * 2;   // bytes per stage (K+V)
    const uint32_t vOffB  = 64 * AST * 2;       // V offset within stage

    // issue K/V tile kt into stage s (16 cp.async, one group)
    auto issue = [&](int kt, int s) {
        const size_t base = ((size_t)(b * TT + kt * 64)) * 512 + hk * 128;
        uint32_t sk = aKV + (uint32_t)s * stageB;
        #pragma unroll
        for (int j = 0; j < 8; ++j) {
            int idx = j * 128 + tid;
            int r = idx >> 4, c = (idx & 15) << 3;
            size_t g = base + (size_t)r * 512 + c;
            uint32_t so = (uint32_t)(r * AST + c) * 2;
            cp_async16(sk + so, Kf + g);
            cp_async16(sk + vOffB + so, Vf + g);
        }
        CP_COMMIT();
    };

    issue(0, 0);

    // load Q tile (plain loads; covered by first barrier)
    {
        const __half* gq = Qf + ((size_t)(b * TT + qBase)) * 2048 + h * 128;
        for (int idx = tid; idx < 1024; idx += 128) {
            int r = idx >> 4, c = (idx & 15) << 3;
            *(uint4*)&sQ[r * AST + c] = *(const uint4*)(gq + (size_t)r * 2048 + c);
        }
    }

    float oacc[16][4];
    #pragma unroll
    for (int i = 0; i < 16; ++i)
        #pragma unroll
        for (int r = 0; r < 4; ++r) oacc[i][r] = 0.f;
    float mrow[2] = {-INFINITY, -INFINITY};
    float lrow[2] = {0.f, 0.f};

    for (int kt = 0; kt <= qt; ++kt) {
        __syncthreads();                       // everyone done with stage kt&1's prior use
        if (kt + 1 <= qt) { issue(kt + 1, (kt + 1) & 1); CP_WAIT1(); }
        else              { CP_WAIT0(); }
        __syncthreads();

        const uint32_t aK = aKV + (uint32_t)(kt & 1) * stageB;
        const uint32_t aV = aK + vOffB;

        // ---- S = Q K^T ----
        float sacc[8][4];
        #pragma unroll
        for (int i = 0; i < 8; ++i)
            #pragma unroll
            for (int r = 0; r < 4; ++r) sacc[i][r] = 0.f;

        #pragma unroll
        for (int ks = 0; ks < 8; ++ks) {
            uint32_t aq[4];
            uint32_t qoff = ((wm * 16 + ldRow) * AST + ks * 16 + ldCol) * 2;
            ldm_x4(aq[0], aq[1], aq[2], aq[3], aQ + qoff);
            #pragma unroll
            for (int j = 0; j < 4; ++j) {
                uint32_t koff = ((j * 16 + ldRow) * AST + ks * 16 + ldCol) * 2;
                uint32_t r0, r1, r2, r3;
                ldm_x4(r0, r1, r2, r3, aK + koff);
                uint32_t b0[2] = {r0, r2}, b1[2] = {r1, r3};
                mma16816(sacc[2 * j], aq, b0);
                mma16816(sacc[2 * j + 1], aq, b1);
            }
        }

        // ---- causal mask (diagonal tile only) ----
        if (kt == qt) {
            int lr0 = wm * 16 + gid, lr1 = lr0 + 8;
            #pragma unroll
            for (int nb = 0; nb < 8; ++nb) {
                int lc = nb * 8 + tig * 2;
                if (lc > lr0)     sacc[nb][0] = -1e30f;
                if (lc + 1 > lr0) sacc[nb][1] = -1e30f;
                if (lc > lr1)     sacc[nb][2] = -1e30f;
                if (lc + 1 > lr1) sacc[nb][3] = -1e30f;
            }
        }

        // ---- online softmax ----
        #pragma unroll
        for (int hf = 0; hf < 2; ++hf) {
            float rmax = -1e30f;
            #pragma unroll
            for (int nb = 0; nb < 8; ++nb)
                rmax = fmaxf(rmax, fmaxf(sacc[nb][hf * 2], sacc[nb][hf * 2 + 1]));
            rmax = fmaxf(rmax, __shfl_xor_sync(0xffffffffu, rmax, 1));
            rmax = fmaxf(rmax, __shfl_xor_sync(0xffffffffu, rmax, 2));
            float mnew = fmaxf(mrow[hf], rmax);
            float f = __expf(mrow[hf] - mnew);
            mrow[hf] = mnew;
            float rsum = 0.f;
            #pragma unroll
            for (int nb = 0; nb < 8; ++nb) {
                float s0 = __expf(sacc[nb][hf * 2] - mnew);
                float s1 = __expf(sacc[nb][hf * 2 + 1] - mnew);
                sacc[nb][hf * 2] = s0;
                sacc[nb][hf * 2 + 1] = s1;
                rsum += s0 + s1;
            }
            rsum += __shfl_xor_sync(0xffffffffu, rsum, 1);
            rsum += __shfl_xor_sync(0xffffffffu, rsum, 2);
            lrow[hf] = lrow[hf] * f + rsum;
            #pragma unroll
            for (int nb = 0; nb < 16; ++nb) {
                oacc[nb][hf * 2] *= f;
                oacc[nb][hf * 2 + 1] *= f;
            }
        }

        // ---- P -> fp16 A-fragments ----
        uint32_t ph[4][4];
        #pragma unroll
        for (int ks = 0; ks < 4; ++ks) {
            ph[ks][0] = pack_h2(sacc[2 * ks][0], sacc[2 * ks][1]);
            ph[ks][1] = pack_h2(sacc[2 * ks][2], sacc[2 * ks][3]);
            ph[ks][2] = pack_h2(sacc[2 * ks + 1][0], sacc[2 * ks + 1][1]);
            ph[ks][3] = pack_h2(sacc[2 * ks + 1][2], sacc[2 * ks + 1][3]);
        }

        // ---- O += P V ----
        #pragma unroll
        for (int ks = 0; ks < 4; ++ks) {
            #pragma unroll
            for (int j = 0; j < 8; ++j) {
                uint32_t voff = ((ks * 16 + ldRow) * AST + j * 16 + ldCol) * 2;
                uint32_t r0, r1, r2, r3;
                ldm_x4t(r0, r1, r2, r3, aV + voff);
                uint32_t v0[2] = {r0, r1}, v1[2] = {r2, r3};
                mma16816(oacc[2 * j], ph[ks], v0);
                mma16816(oacc[2 * j + 1], ph[ks], v1);
            }
        }
    }

    // ---- epilogue ----
    float inv0 = 1.f / lrow[0], inv1 = 1.f / lrow[1];
    size_t row0 = (size_t)(b * TT + qBase + wm * 16 + gid);
    __half* p0 = Oo + row0 * KDIM + h * 128 + tig * 2;
    __half* p1 = Oo + (row0 + 8) * KDIM + h * 128 + tig * 2;
    #pragma unroll
    for (int nb = 0; nb < 16; ++nb) {
        *(uint32_t*)(p0 + nb * 8) = pack_h2(oacc[nb][0] * inv0, oacc[nb][1] * inv0);
        *(uint32_t*)(p1 + nb * 8) = pack_h2(oacc[nb][2] * inv1, oacc[nb][3] * inv1);
    }
}

// ---------------- launcher ---------------------------------------------------
extern "C" void kernel_launch(void* const* d_in, const int* in_sizes, int n_in,
                              void* d_out, int out_size)
{
    const float* x  = (const float*)d_in[0];
    const float* wq = (const float*)d_in[1];
    const float* wk = (const float*)d_in[2];
    const float* wv = (const float*)d_in[3];
    const float* wo = (const float*)d_in[4];
    float* out = (float*)d_out;

    float *QKV;
    __half *xh, *ah, *wqkvt, *wot, *qf, *kf, *vf;
    cudaGetSymbolAddress((void**)&QKV, g_QKV);
    cudaGetSymbolAddress((void**)&xh, g_xh);
    cudaGetSymbolAddress((void**)&ah, g_ah);
    cudaGetSymbolAddress((void**)&wqkvt, g_wqkvt);
    cudaGetSymbolAddress((void**)&wot, g_wot);
    cudaGetSymbolAddress((void**)&qf, g_Qf);
    cudaGetSymbolAddress((void**)&kf, g_Kf);
    cudaGetSymbolAddress((void**)&vf, g_Vf);

    cudaFuncSetAttribute(attn_mma_kernel,
                         cudaFuncAttributeMaxDynamicSharedMemorySize, ATT_SMEM);
    cudaFuncSetAttribute(gemm_kernel,
                         cudaFuncAttributeMaxDynamicSharedMemorySize, G_SMEM_B);

    // weight conversions into fused buffer (Q rows 0..2047, K 2048..2559, V 2560..3071)
    tconv_kernel<<<dim3(2048 / 32, KDIM / 32), 256>>>(wq, wqkvt, 2048);
    tconv_kernel<<<dim3(512 / 32,  KDIM / 32), 256>>>(wk, wqkvt + (size_t)2048 * KDIM, 512);
    tconv_kernel<<<dim3(512 / 32,  KDIM / 32), 256>>>(wv, wqkvt + (size_t)2560 * KDIM, 512);
    tconv_kernel<<<dim3(2048 / 32, KDIM / 32), 256>>>(wo, wot, 2048);
    conv4_kernel<<<(BT * KDIM / 4 + 255) / 256, 256>>>(x, xh, BT * KDIM / 4);

    // fused QKV projection: one GEMM, N=3072
    gemm_kernel<<<dim3(NQKV / 128, BT / 128), 256, G_SMEM_B>>>(xh, wqkvt, QKV, NQKV, KDIM);

    // RoPE table + RoPE/convert (Q pre-scaled by 1/sqrt(128)); V convert
    rope_table_kernel<<<(TT * 64 + 255) / 256, 256>>>();
    rope_conv_kernel<<<(BT * 1024 + 255) / 256, 256>>>(QKV, qf, 2048, NQKV,
                                                       0.08838834764831845f);
    rope_conv_kernel<<<(BT * 256 + 255) / 256, 256>>>(QKV + 2048, kf, 512, NQKV, 1.0f);
    conv4s_kernel<<<(BT * 128 + 255) / 256, 256>>>(QKV + 2560, vf, 128, NQKV);

    // fp16 tensor-core flash attention -> ah
    attn_mma_kernel<<<dim3(TT / 64, NH, BB), 128, ATT_SMEM>>>(qf, kf, vf, ah);

    // Output projection
    gemm_kernel<<<dim3(2048 / 128, BT / 128), 256, G_SMEM_B>>>(ah, wot, out, 2048, KDIM);
}

// round 13
// speedup vs baseline: 8.3663x; 1.0158x over previous
#include <cuda_runtime.h>
#include <cuda_fp16.h>
#include <math.h>
#include <stdint.h>

#define BB   2
#define TT   2048
#define DD   2048
#define NH   16
#define NKV  4
#define HDQ  128
#define BT   4096   // BB*TT
#define KDIM 2048
#define NQKV 3072   // fused Q(2048)+K(512)+V(512) output width
#define QSCALE 0.08838834764831845f

// ---------------- scratch (static device globals: no allocs allowed) --------
__device__ __half g_xh[(size_t)BT * KDIM];        // x fp16 [M][K]
__device__ __half g_ah[(size_t)BT * KDIM];        // attn-out fp16 [M][K]
__device__ __half g_wqkvt[(size_t)NQKV * KDIM];   // fused [N][K] fp16 weights
__device__ __half g_wot[(size_t)2048 * KDIM];
__device__ float g_rcos[TT * 64];
__device__ float g_rsin[TT * 64];

// attention operands fp16
__device__ __half g_Qf[(size_t)BT * 2048];
__device__ __half g_Kf[(size_t)BT * 512];
__device__ __half g_Vf[(size_t)BT * 512];

// ---------------- helpers ----------------------------------------------------
__device__ __forceinline__ uint32_t smem_u32(const void* p) {
    uint32_t a;
    asm("{ .reg .u64 t; cvta.to.shared.u64 t, %1; cvt.u32.u64 %0, t; }"
        : "=r"(a) : "l"(p));
    return a;
}
__device__ __forceinline__ void ldm_x4(uint32_t& r0, uint32_t& r1,
                                       uint32_t& r2, uint32_t& r3, uint32_t addr) {
    asm volatile("ldmatrix.sync.aligned.m8n8.x4.shared.b16 {%0,%1,%2,%3}, [%4];"
                 : "=r"(r0), "=r"(r1), "=r"(r2), "=r"(r3) : "r"(addr));
}
__device__ __forceinline__ void ldm_x4t(uint32_t& r0, uint32_t& r1,
                                        uint32_t& r2, uint32_t& r3, uint32_t addr) {
    asm volatile("ldmatrix.sync.aligned.m8n8.x4.trans.shared.b16 {%0,%1,%2,%3}, [%4];"
                 : "=r"(r0), "=r"(r1), "=r"(r2), "=r"(r3) : "r"(addr));
}
__device__ __forceinline__ void mma16816(float* d, const uint32_t* a, const uint32_t* b) {
    asm volatile("mma.sync.aligned.m16n8k16.row.col.f32.f16.f16.f32 "
                 "{%0,%1,%2,%3}, {%4,%5,%6,%7}, {%8,%9}, {%0,%1,%2,%3};"
                 : "+f"(d[0]), "+f"(d[1]), "+f"(d[2]), "+f"(d[3])
                 : "r"(a[0]), "r"(a[1]), "r"(a[2]), "r"(a[3]),
                   "r"(b[0]), "r"(b[1]));
}
__device__ __forceinline__ void cp_async16(uint32_t saddr, const void* gaddr) {
    asm volatile("cp.async.cg.shared.global [%0], [%1], 16;"
                 :: "r"(saddr), "l"(gaddr) : "memory");
}
#define CP_COMMIT() asm volatile("cp.async.commit_group;" ::: "memory")
#define CP_WAIT1()  asm volatile("cp.async.wait_group 1;" ::: "memory")
#define CP_WAIT0()  asm volatile("cp.async.wait_group 0;" ::: "memory")

__device__ __forceinline__ uint32_t pack_h2(float a, float b) {
    __half2 t = __floats2half2_rn(a, b);
    return *reinterpret_cast<uint32_t*>(&t);
}

// ---------------- conversion kernels ----------------------------------------
__global__ void conv4_kernel(const float* __restrict__ A, __half* __restrict__ O, int n4)
{
    int idx = blockIdx.x * blockDim.x + threadIdx.x;
    if (idx >= n4) return;
    float4 v = ((const float4*)A)[idx];
    __half2 a = __floats2half2_rn(v.x, v.y);
    __half2 b = __floats2half2_rn(v.z, v.w);
    uint2 o = make_uint2(*reinterpret_cast<uint32_t*>(&a),
                         *reinterpret_cast<uint32_t*>(&b));
    ((uint2*)O)[idx] = o;
}
// transpose+convert: W[K=2048][N] fp32 -> Wt[N][K] fp16
__global__ void tconv_kernel(const float* __restrict__ W, __half* __restrict__ Wt, int N)
{
    __shared__ float tile[32][33];
    int tx = threadIdx.x & 31, ty = threadIdx.x >> 5;
    int nb = blockIdx.x * 32, kb = blockIdx.y * 32;
    #pragma unroll
    for (int r = 0; r < 4; ++r)
        tile[ty + r * 8][tx] = W[(size_t)(kb + ty + r * 8) * N + nb + tx];
    __syncthreads();
    #pragma unroll
    for (int r = 0; r < 4; ++r) {
        int n = nb + ty + r * 8;
        Wt[(size_t)n * KDIM + kb + tx] = __float2half(tile[tx][ty + r * 8]);
    }
}
__global__ void rope_table_kernel()
{
    int idx = blockIdx.x * blockDim.x + threadIdx.x;
    if (idx >= TT * 64) return;
    int t = idx >> 6, d = idx & 63;
    double inv = exp2(-(double)d * (19.931568569324174 / 64.0));
    double ang = (double)t * inv;
    g_rcos[idx] = (float)cos(ang);
    g_rsin[idx] = (float)sin(ang);
}

// ---------------- shared GEMM mainloop (macro-free via inline) ---------------
#define GSTAGE_H   (128 * 40)
#define G_PIPE_B   (6 * GSTAGE_H * 2)          // 61440 bytes
#define G_EPI_B    (128 * 132 * 4)             // 67584 bytes (fp32 C tile)
#define G_SMEM_B   (G_EPI_B)                   // max(pipe, epi)

// mainloop computing acc for one 128x128 tile; smem base smb
__device__ __forceinline__ void gemm_mainloop(
    const __half* __restrict__ A, const __half* __restrict__ Bt,
    int mBase, int nBase, int K, uint32_t smb,
    int tid, int lane, int wm, int wn, float acc[2][8][4])
{
    const int NC = K >> 5;
    const int lrow = tid >> 1;
    const int lseg = (tid & 1) << 4;
    const int ldRow = lane & 15;
    const int ldCol = (lane >> 4) << 3;

    const __half* gA = A  + (size_t)(mBase + lrow) * K + lseg;
    const __half* gB = Bt + (size_t)(nBase + lrow) * K + lseg;
    const uint32_t sOff = (uint32_t)(lrow * 40 + lseg) * 2;

    auto issue = [&](int c, int s) {
        const __half* ga = gA + c * 32;
        const __half* gb = gB + c * 32;
        uint32_t sa = smb + (uint32_t)s * (GSTAGE_H * 2) + sOff;
        uint32_t sb = smb + (uint32_t)(3 * GSTAGE_H * 2) + (uint32_t)s * (GSTAGE_H * 2) + sOff;
        cp_async16(sa,      ga);
        cp_async16(sa + 16, ga + 8);
        cp_async16(sb,      gb);
        cp_async16(sb + 16, gb + 8);
        CP_COMMIT();
    };

    issue(0, 0);
    issue(1, 1);

    int stage = 0;
    for (int c = 0; c < NC; ++c) {
        if (c + 1 < NC) CP_WAIT1(); else CP_WAIT0();
        __syncthreads();
        if (c + 2 < NC) {
            int ns = stage + 2; if (ns >= 3) ns -= 3;
            issue(c + 2, ns);
        }
        const uint32_t sA = smb + (uint32_t)stage * (GSTAGE_H * 2);
        const uint32_t sB = smb + (uint32_t)(3 * GSTAGE_H * 2) + (uint32_t)stage * (GSTAGE_H * 2);
        #pragma unroll
        for (int ks = 0; ks < 2; ++ks) {
            uint32_t af[2][4], bfr[8][2];
            #pragma unroll
            for (int mf = 0; mf < 2; ++mf) {
                uint32_t addr = sA + ((wm * 32 + mf * 16 + ldRow) * 40
                                      + ks * 16 + ldCol) * 2;
                ldm_x4(af[mf][0], af[mf][1], af[mf][2], af[mf][3], addr);
            }
            #pragma unroll
            for (int ng = 0; ng < 4; ++ng) {
                uint32_t r0, r1, r2, r3;
                uint32_t addr = sB + ((wn * 64 + ng * 16 + ldRow) * 40
                                      + ks * 16 + ldCol) * 2;
                ldm_x4(r0, r1, r2, r3, addr);
                bfr[ng * 2 + 0][0] = r0; bfr[ng * 2 + 1][0] = r1;
                bfr[ng * 2 + 0][1] = r2; bfr[ng * 2 + 1][1] = r3;
            }
            #pragma unroll
            for (int mf = 0; mf < 2; ++mf)
                #pragma unroll
                for (int nf = 0; nf < 8; ++nf)
                    mma16816(acc[mf][nf], af[mf], bfr[nf]);
        }
        ++stage; if (stage == 3) stage = 0;
    }
}

// ---------------- GEMM with plain fp32 epilogue (output projection) ----------
__global__ __launch_bounds__(256, 2) void gemm_kernel(
    const __half* __restrict__ A, const __half* __restrict__ Bt,
    float* __restrict__ C, int N, int K)
{
    extern __shared__ __half gsm[];
    const uint32_t smb = smem_u32(gsm);
    const int tid = threadIdx.x;
    const int lane = tid & 31, wid = tid >> 5;
    const int wm = wid & 3, wn = wid >> 2;
    const int mBase = blockIdx.y << 7, nBase = blockIdx.x << 7;

    float acc[2][8][4];
    #pragma unroll
    for (int i = 0; i < 2; ++i)
        #pragma unroll
        for (int j = 0; j < 8; ++j)
            #pragma unroll
            for (int r = 0; r < 4; ++r) acc[i][j][r] = 0.f;

    gemm_mainloop(A, Bt, mBase, nBase, K, smb, tid, lane, wm, wn, acc);

    const int gid = lane >> 2, tig = lane & 3;
    #pragma unroll
    for (int mf = 0; mf < 2; ++mf) {
        #pragma unroll
        for (int nf = 0; nf < 8; ++nf) {
            int row = mBase + wm * 32 + mf * 16 + gid;
            int col = nBase + wn * 64 + nf * 8 + tig * 2;
            float2 v0 = make_float2(acc[mf][nf][0], acc[mf][nf][1]);
            float2 v1 = make_float2(acc[mf][nf][2], acc[mf][nf][3]);
            *(float2*)&C[(size_t)row * N + col] = v0;
            *(float2*)&C[(size_t)(row + 8) * N + col] = v1;
        }
    }
}

// ---------------- fused QKV GEMM: rope + fp16 convert in epilogue ------------
// nBase < 2048: Q head (rope, scale) -> qf; [2048,2560): K head (rope) -> kf;
// >= 2560: V (convert only) -> vf.
__global__ __launch_bounds__(256, 2) void gemm_qkv_kernel(
    const __half* __restrict__ A, const __half* __restrict__ Bt,
    __half* __restrict__ qf, __half* __restrict__ kf, __half* __restrict__ vf,
    int K)
{
    extern __shared__ __half gsm[];
    const uint32_t smb = smem_u32(gsm);
    const int tid = threadIdx.x;
    const int lane = tid & 31, wid = tid >> 5;
    const int wm = wid & 3, wn = wid >> 2;
    const int mBase = blockIdx.y << 7, nBase = blockIdx.x << 7;

    float acc[2][8][4];
    #pragma unroll
    for (int i = 0; i < 2; ++i)
        #pragma unroll
        for (int j = 0; j < 8; ++j)
            #pragma unroll
            for (int r = 0; r < 4; ++r) acc[i][j][r] = 0.f;

    gemm_mainloop(A, Bt, mBase, nBase, K, smb, tid, lane, wm, wn, acc);

    // stage fp32 C tile in smem (reuse pipeline buffers)
    float* Cs = (float*)gsm;
    __syncthreads();
    const int gid = lane >> 2, tig = lane & 3;
    #pragma unroll
    for (int mf = 0; mf < 2; ++mf) {
        #pragma unroll
        for (int nf = 0; nf < 8; ++nf) {
            int r = wm * 32 + mf * 16 + gid;
            int col = wn * 64 + nf * 8 + tig * 2;
            *(float2*)&Cs[r * 132 + col] = make_float2(acc[mf][nf][0], acc[mf][nf][1]);
            *(float2*)&Cs[(r + 8) * 132 + col] = make_float2(acc[mf][nf][2], acc[mf][nf][3]);
        }
    }
    __syncthreads();

    if (nBase < 2048) {                    // Q head: rope + scale
        for (int p = tid; p < 128 * 64; p += 256) {
            int r = p >> 6, d = p & 63;
            int row = mBase + r;
            int t = row & (TT - 1);
            float c = g_rcos[t * 64 + d], s = g_rsin[t * 64 + d];
            float u1 = Cs[r * 132 + d], u2 = Cs[r * 132 + d + 64];
            __half* op = qf + (size_t)row * 2048 + nBase;
            op[d]      = __float2half((u1 * c - u2 * s) * QSCALE);
            op[d + 64] = __float2half((u2 * c + u1 * s) * QSCALE);
        }
    } else if (nBase < 2560) {             // K head: rope
        int colb = nBase - 2048;
        for (int p = tid; p < 128 * 64; p += 256) {
            int r = p >> 6, d = p & 63;
            int row = mBase + r;
            int t = row & (TT - 1);
            float c = g_rcos[t * 64 + d], s = g_rsin[t * 64 + d];
            float u1 = Cs[r * 132 + d], u2 = Cs[r * 132 + d + 64];
            __half* op = kf + (size_t)row * 512 + colb;
            op[d]      = __float2half(u1 * c - u2 * s);
            op[d + 64] = __float2half(u2 * c + u1 * s);
        }
    } else {                               // V: plain convert
        int colb = nBase - 2560;
        for (int p = tid; p < 128 * 128; p += 256) {
            int r = p >> 7, d = p & 127;
            int row = mBase + r;
            vf[(size_t)row * 512 + colb + d] = __float2half(Cs[r * 132 + d]);
        }
    }
}

// ---------------- fp16 tensor-core flash attention (2-stage K/V pipeline) ----
#define AST 136
#define ATT_SMEM (5 * 64 * AST * 2)   // Q + 2 x (K,V) stages = 87040 B

__global__ __launch_bounds__(128) void attn_mma_kernel(
    const __half* __restrict__ Qf, const __half* __restrict__ Kf,
    const __half* __restrict__ Vf, __half* __restrict__ Oo)
{
    extern __shared__ __half smh[];
    __half* sQ = smh;
    __half* sKV = sQ + 64 * AST;

    const int tid = threadIdx.x;
    const int lane = tid & 31, wm = tid >> 5;
    const int gid = lane >> 2, tig = lane & 3;
    const int ldRow = lane & 15, ldCol = (lane >> 4) << 3;
    const int qt = gridDim.x - 1 - blockIdx.x;
    const int h = blockIdx.y, b = blockIdx.z;
    const int hk = h >> 2;
    const int qBase = qt * 64;

    const uint32_t aQ = smem_u32(sQ);
    const uint32_t aKV = smem_u32(sKV);
    const uint32_t stageB = 2 * 64 * AST * 2;
    const uint32_t vOffB  = 64 * AST * 2;

    auto issue = [&](int kt, int s) {
        const size_t base = ((size_t)(b * TT + kt * 64)) * 512 + hk * 128;
        uint32_t sk = aKV + (uint32_t)s * stageB;
        #pragma unroll
        for (int j = 0; j < 8; ++j) {
            int idx = j * 128 + tid;
            int r = idx >> 4, c = (idx & 15) << 3;
            size_t g = base + (size_t)r * 512 + c;
            uint32_t so = (uint32_t)(r * AST + c) * 2;
            cp_async16(sk + so, Kf + g);
            cp_async16(sk + vOffB + so, Vf + g);
        }
        CP_COMMIT();
    };

    issue(0, 0);

    {
        const __half* gq = Qf + ((size_t)(b * TT + qBase)) * 2048 + h * 128;
        for (int idx = tid; idx < 1024; idx += 128) {
            int r = idx >> 4, c = (idx & 15) << 3;
            *(uint4*)&sQ[r * AST + c] = *(const uint4*)(gq + (size_t)r * 2048 + c);
        }
    }

    float oacc[16][4];
    #pragma unroll
    for (int i = 0; i < 16; ++i)
        #pragma unroll
        for (int r = 0; r < 4; ++r) oacc[i][r] = 0.f;
    float mrow[2] = {-INFINITY, -INFINITY};
    float lrow[2] = {0.f, 0.f};

    for (int kt = 0; kt <= qt; ++kt) {
        __syncthreads();
        if (kt + 1 <= qt) { issue(kt + 1, (kt + 1) & 1); CP_WAIT1(); }
        else              { CP_WAIT0(); }
        __syncthreads();

        const uint32_t aK = aKV + (uint32_t)(kt & 1) * stageB;
        const uint32_t aV = aK + vOffB;

        float sacc[8][4];
        #pragma unroll
        for (int i = 0; i < 8; ++i)
            #pragma unroll
            for (int r = 0; r < 4; ++r) sacc[i][r] = 0.f;

        #pragma unroll
        for (int ks = 0; ks < 8; ++ks) {
            uint32_t aq[4];
            uint32_t qoff = ((wm * 16 + ldRow) * AST + ks * 16 + ldCol) * 2;
            ldm_x4(aq[0], aq[1], aq[2], aq[3], aQ + qoff);
            #pragma unroll
            for (int j = 0; j < 4; ++j) {
                uint32_t koff = ((j * 16 + ldRow) * AST + ks * 16 + ldCol) * 2;
                uint32_t r0, r1, r2, r3;
                ldm_x4(r0, r1, r2, r3, aK + koff);
                uint32_t b0[2] = {r0, r2}, b1[2] = {r1, r3};
                mma16816(sacc[2 * j], aq, b0);
                mma16816(sacc[2 * j + 1], aq, b1);
            }
        }

        if (kt == qt) {
            int lr0 = wm * 16 + gid, lr1 = lr0 + 8;
            #pragma unroll
            for (int nb = 0; nb < 8; ++nb) {
                int lc = nb * 8 + tig * 2;
                if (lc > lr0)     sacc[nb][0] = -1e30f;
                if (lc + 1 > lr0) sacc[nb][1] = -1e30f;
                if (lc > lr1)     sacc[nb][2] = -1e30f;
                if (lc + 1 > lr1) sacc[nb][3] = -1e30f;
            }
        }

        #pragma unroll
        for (int hf = 0; hf < 2; ++hf) {
            float rmax = -1e30f;
            #pragma unroll
            for (int nb = 0; nb < 8; ++nb)
                rmax = fmaxf(rmax, fmaxf(sacc[nb][hf * 2], sacc[nb][hf * 2 + 1]));
            rmax = fmaxf(rmax, __shfl_xor_sync(0xffffffffu, rmax, 1));
            rmax = fmaxf(rmax, __shfl_xor_sync(0xffffffffu, rmax, 2));
            float mnew = fmaxf(mrow[hf], rmax);
            float f = __expf(mrow[hf] - mnew);
            mrow[hf] = mnew;
            float rsum = 0.f;
            #pragma unroll
            for (int nb = 0; nb < 8; ++nb) {
                float s0 = __expf(sacc[nb][hf * 2] - mnew);
                float s1 = __expf(sacc[nb][hf * 2 + 1] - mnew);
                sacc[nb][hf * 2] = s0;
                sacc[nb][hf * 2 + 1] = s1;
                rsum += s0 + s1;
            }
            rsum += __shfl_xor_sync(0xffffffffu, rsum, 1);
            rsum += __shfl_xor_sync(0xffffffffu, rsum, 2);
            lrow[hf] = lrow[hf] * f + rsum;
            #pragma unroll
            for (int nb = 0; nb < 16; ++nb) {
                oacc[nb][hf * 2] *= f;
                oacc[nb][hf * 2 + 1] *= f;
            }
        }

        uint32_t ph[4][4];
        #pragma unroll
        for (int ks = 0; ks < 4; ++ks) {
            ph[ks][0] = pack_h2(sacc[2 * ks][0], sacc[2 * ks][1]);
            ph[ks][1] = pack_h2(sacc[2 * ks][2], sacc[2 * ks][3]);
            ph[ks][2] = pack_h2(sacc[2 * ks + 1][0], sacc[2 * ks + 1][1]);
            ph[ks][3] = pack_h2(sacc[2 * ks + 1][2], sacc[2 * ks + 1][3]);
        }

        #pragma unroll
        for (int ks = 0; ks < 4; ++ks) {
            #pragma unroll
            for (int j = 0; j < 8; ++j) {
                uint32_t voff = ((ks * 16 + ldRow) * AST + j * 16 + ldCol) * 2;
                uint32_t r0, r1, r2, r3;
                ldm_x4t(r0, r1, r2, r3, aV + voff);
                uint32_t v0[2] = {r0, r1}, v1[2] = {r2, r3};
                mma16816(oacc[2 * j], ph[ks], v0);
                mma16816(oacc[2 * j + 1], ph[ks], v1);
            }
        }
    }

    float inv0 = 1.f / lrow[0], inv1 = 1.f / lrow[1];
    size_t row0 = (size_t)(b * TT + qBase + wm * 16 + gid);
    __half* p0 = Oo + row0 * KDIM + h * 128 + tig * 2;
    __half* p1 = Oo + (row0 + 8) * KDIM + h * 128 + tig * 2;
    #pragma unroll
    for (int nb = 0; nb < 16; ++nb) {
        *(uint32_t*)(p0 + nb * 8) = pack_h2(oacc[nb][0] * inv0, oacc[nb][1] * inv0);
        *(uint32_t*)(p1 + nb * 8) = pack_h2(oacc[nb][2] * inv1, oacc[nb][3] * inv1);
    }
}

// ---------------- launcher ---------------------------------------------------
extern "C" void kernel_launch(void* const* d_in, const int* in_sizes, int n_in,
                              void* d_out, int out_size)
{
    const float* x  = (const float*)d_in[0];
    const float* wq = (const float*)d_in[1];
    const float* wk = (const float*)d_in[2];
    const float* wv = (const float*)d_in[3];
    const float* wo = (const float*)d_in[4];
    float* out = (float*)d_out;

    __half *xh, *ah, *wqkvt, *wot, *qf, *kf, *vf;
    cudaGetSymbolAddress((void**)&xh, g_xh);
    cudaGetSymbolAddress((void**)&ah, g_ah);
    cudaGetSymbolAddress((void**)&wqkvt, g_wqkvt);
    cudaGetSymbolAddress((void**)&wot, g_wot);
    cudaGetSymbolAddress((void**)&qf, g_Qf);
    cudaGetSymbolAddress((void**)&kf, g_Kf);
    cudaGetSymbolAddress((void**)&vf, g_Vf);

    cudaFuncSetAttribute(attn_mma_kernel,
                         cudaFuncAttributeMaxDynamicSharedMemorySize, ATT_SMEM);
    cudaFuncSetAttribute(gemm_kernel,
                         cudaFuncAttributeMaxDynamicSharedMemorySize, G_SMEM_B);
    cudaFuncSetAttribute(gemm_qkv_kernel,
                         cudaFuncAttributeMaxDynamicSharedMemorySize, G_SMEM_B);

    // rope table + conversions
    rope_table_kernel<<<(TT * 64 + 255) / 256, 256>>>();
    tconv_kernel<<<dim3(2048 / 32, KDIM / 32), 256>>>(wq, wqkvt, 2048);
    tconv_kernel<<<dim3(512 / 32,  KDIM / 32), 256>>>(wk, wqkvt + (size_t)2048 * KDIM, 512);
    tconv_kernel<<<dim3(512 / 32,  KDIM / 32), 256>>>(wv, wqkvt + (size_t)2560 * KDIM, 512);
    tconv_kernel<<<dim3(2048 / 32, KDIM / 32), 256>>>(wo, wot, 2048);
    conv4_kernel<<<(BT * KDIM / 4 + 255) / 256, 256>>>(x, xh, BT * KDIM / 4);

    // fused QKV projection + rope + fp16 convert (one GEMM, N=3072)
    gemm_qkv_kernel<<<dim3(NQKV / 128, BT / 128), 256, G_SMEM_B>>>(xh, wqkvt,
                                                                   qf, kf, vf, KDIM);

    // fp16 tensor-core flash attention -> ah
    attn_mma_kernel<<<dim3(TT / 64, NH, BB), 128, ATT_SMEM>>>(qf, kf, vf, ah);

    // Output projection (fp32 out)
    gemm_kernel<<<dim3(2048 / 128, BT / 128), 256, G_SMEM_B>>>(ah, wot, out, 2048, KDIM);
}